// round 12
// baseline (speedup 1.0000x reference)
#include <cuda_runtime.h>
#include <cuda_bf16.h>
#include <math.h>
#include <stdint.h>

// ---------------------------------------------------------------- dims
#define BSZ 4
#define SEQ 4096
#define DM  512
#define NROWS (BSZ * SEQ)                 // 16384
#define NTH 256
#define BM 128
#define BN 128
#define BK 32
#define SOFTMAX_SCALE 0.04419417382415922f

// smem stage layout (bf16 tiles, 64-byte rows, SW64 swizzle)
// regions within a stage: AH 0, AL 8192, BH 16384, BL 24576
#define STAGE 32768
#define NSTAGE 3
#define SMEM_TOTAL (NSTAGE * STAGE)       // 98304 bytes -> 2 CTAs/SM

#define SW64(o) ((uint32_t)(o) ^ ((((uint32_t)(o)) >> 3) & 0x30u))

// ---------------------------------------------------------------- scratch
__device__ __nv_bfloat16 g_xh[(size_t)NROWS * DM];
__device__ __nv_bfloat16 g_xl[(size_t)NROWS * DM];
__device__ __nv_bfloat16 g_Wvh[DM * DM];    // Wv    [e][d]
__device__ __nv_bfloat16 g_Wvl[DM * DM];
__device__ __nv_bfloat16 g_MTh[DM * DM];    // (Wq^T Wk)^T * scale  [e][d]
__device__ __nv_bfloat16 g_MTl[DM * DM];
__device__ __nv_bfloat16 g_Gh[(size_t)NROWS * DM];   // G = x*M*scale
__device__ __nv_bfloat16 g_Gl[(size_t)NROWS * DM];
__device__ __nv_bfloat16 g_Vth[(size_t)BSZ * DM * SEQ];  // V^T [b][d][s]
__device__ __nv_bfloat16 g_Vtl[(size_t)BSZ * DM * SEQ];
__device__ __nv_bfloat16 g_Ph[(size_t)BSZ * SEQ * SEQ];  // probs hi/lo
__device__ __nv_bfloat16 g_Pl[(size_t)BSZ * SEQ * SEQ];

// ---------------------------------------------------------------- helpers
__device__ __forceinline__ uint32_t smem_u32(const void* p) {
    return (uint32_t)__cvta_generic_to_shared(p);
}
__device__ __forceinline__ void ldmx4(uint32_t r[4], uint32_t addr) {
    asm volatile("ldmatrix.sync.aligned.m8n8.x4.shared.b16 {%0,%1,%2,%3}, [%4];"
                 : "=r"(r[0]), "=r"(r[1]), "=r"(r[2]), "=r"(r[3]) : "r"(addr));
}
__device__ __forceinline__ void mma16816(float d[4], const uint32_t a[4],
                                         uint32_t b0, uint32_t b1) {
    asm volatile("mma.sync.aligned.m16n8k16.row.col.f32.bf16.bf16.f32 "
                 "{%0,%1,%2,%3}, {%4,%5,%6,%7}, {%8,%9}, {%0,%1,%2,%3};"
                 : "+f"(d[0]), "+f"(d[1]), "+f"(d[2]), "+f"(d[3])
                 : "r"(a[0]), "r"(a[1]), "r"(a[2]), "r"(a[3]), "r"(b0), "r"(b1));
}
__device__ __forceinline__ void cpasync16(uint32_t dst, const void* src) {
    asm volatile("cp.async.cg.shared.global [%0], [%1], 16;" :: "r"(dst), "l"(src));
}
#define CP_COMMIT() asm volatile("cp.async.commit_group;")
#define CP_WAIT(N)  asm volatile("cp.async.wait_group %0;" :: "n"(N))

__device__ __forceinline__ void split_bf16(float v, uint16_t& h, uint16_t& l) {
    __nv_bfloat16 hb = __float2bfloat16(v);
    float r = v - __bfloat162float(hb);
    h = __bfloat16_as_ushort(hb);
    l = __bfloat16_as_ushort(__float2bfloat16(r));
}

// ---------------------------------------------------------------- GEMM engine
// Strength-reduced pipeline: all smem addresses are (2 base offsets + imm).
// ks step uses XOR (swizzle-correct since base column bit5 is clear).
// acc += Ah*Bh + Ah*Bl + Al*Bh over nch chunks of BK=32.
__device__ __forceinline__ void run_gemm(
    uint32_t sb, int t, int wr, int wc, int lane,
    const __nv_bfloat16* Ah, const __nv_bfloat16* Al,
    const __nv_bfloat16* Bh, const __nv_bfloat16* Bl,
    size_t ldA, size_t ldB, int nch, float acc[2][8][4])
{
    const int lrow = t >> 2;
    const int lc8 = (t & 3) << 3;
    const uint32_t sdst = SW64((lrow << 6) + (lc8 << 1));
    const __nv_bfloat16* pAh = Ah + (size_t)lrow * ldA + lc8;
    const __nv_bfloat16* pAl = Al + (size_t)lrow * ldA + lc8;
    const __nv_bfloat16* pBh = Bh + (size_t)lrow * ldB + lc8;
    const __nv_bfloat16* pBl = Bl + (size_t)lrow * ldB + lc8;
    const size_t a64 = (size_t)64 * ldA;
    const size_t b64 = (size_t)64 * ldB;

    const uint32_t aoff = SW64(((wr * 32 + (lane & 15)) << 6) + (((lane >> 4) << 3) << 1));
    const uint32_t boff = SW64(((wc * 64 + ((lane >> 4) << 3) + (lane & 7)) << 6)
                               + ((((lane >> 3) & 1) << 3) << 1));

    uint32_t s0 = sb, s1 = sb + STAGE, s2 = sb + 2 * STAGE;

#define LOADC(d)                                                                  \
    do {                                                                          \
        cpasync16((d) + sdst,                 pAh);                               \
        cpasync16((d) + sdst + 4096,          pAh + a64);                         \
        cpasync16((d) + 8192 + sdst,          pAl);                               \
        cpasync16((d) + 8192 + sdst + 4096,   pAl + a64);                         \
        cpasync16((d) + 16384 + sdst,         pBh);                               \
        cpasync16((d) + 16384 + sdst + 4096,  pBh + b64);                         \
        cpasync16((d) + 24576 + sdst,         pBl);                               \
        cpasync16((d) + 24576 + sdst + 4096,  pBl + b64);                         \
        pAh += BK; pAl += BK; pBh += BK; pBl += BK;                               \
    } while (0)

    LOADC(s0);
    CP_COMMIT();
    if (nch > 1) LOADC(s1);
    CP_COMMIT();

    for (int c = 0; c < nch; c++) {
        CP_WAIT(1);
        __syncthreads();
        if (c + 2 < nch) LOADC(s2);
        CP_COMMIT();

        #pragma unroll
        for (int ks = 0; ks < 2; ks++) {
            const uint32_t ab = s0 + (aoff ^ (ks << 5));
            const uint32_t bb = s0 + 16384 + (boff ^ (ks << 5));
            uint32_t ah[2][4], al[2][4];
            ldmx4(ah[0], ab);
            ldmx4(ah[1], ab + 1024);
            ldmx4(al[0], ab + 8192);
            ldmx4(al[1], ab + 8192 + 1024);
            #pragma unroll
            for (int p = 0; p < 4; p++) {
                uint32_t bh[4], bl[4];
                ldmx4(bh, bb + p * 1024);
                ldmx4(bl, bb + 8192 + p * 1024);
                #pragma unroll
                for (int mi = 0; mi < 2; mi++) {
                    mma16816(acc[mi][2 * p],     ah[mi], bh[0], bh[1]);
                    mma16816(acc[mi][2 * p + 1], ah[mi], bh[2], bh[3]);
                    mma16816(acc[mi][2 * p],     ah[mi], bl[0], bl[1]);
                    mma16816(acc[mi][2 * p + 1], ah[mi], bl[2], bl[3]);
                    mma16816(acc[mi][2 * p],     al[mi], bh[0], bh[1]);
                    mma16816(acc[mi][2 * p + 1], al[mi], bh[2], bh[3]);
                }
            }
        }
        uint32_t tmp = s0; s0 = s1; s1 = s2; s2 = tmp;
    }
#undef LOADC
}

// ---------------------------------------------------------------- kernel: prep
// bid [0,8192): split x -> g_xh/g_xl
// bid [8192,8448): split Wv -> g_Wvh/g_Wvl
// bid [8448,8512): fp32 M gemm: MT[e][d] = scale * sum_f Wk[f][e] Wq[f][d]
__global__ __launch_bounds__(NTH)
void prep_kernel(const float* __restrict__ x, const float* __restrict__ WQ,
                 const float* __restrict__ WK, const float* __restrict__ WV) {
    __shared__ float sa[32][64];   // Wk chunk [f][e]
    __shared__ float sb_[32][64];  // Wq chunk [f][d]
    const int bid = blockIdx.x;
    const int t = threadIdx.x;

    if (bid < 8192) {
        int i = bid * NTH + t;     // < 2097152 float4
        float4 v = reinterpret_cast<const float4*>(x)[i];
        uint16_t h0, h1, h2, h3, l0, l1, l2, l3;
        split_bf16(v.x, h0, l0); split_bf16(v.y, h1, l1);
        split_bf16(v.z, h2, l2); split_bf16(v.w, h3, l3);
        reinterpret_cast<uint2*>(g_xh)[i] =
            make_uint2((uint32_t)h0 | ((uint32_t)h1 << 16), (uint32_t)h2 | ((uint32_t)h3 << 16));
        reinterpret_cast<uint2*>(g_xl)[i] =
            make_uint2((uint32_t)l0 | ((uint32_t)l1 << 16), (uint32_t)l2 | ((uint32_t)l3 << 16));
        return;
    }
    if (bid < 8448) {
        int i = (bid - 8192) * NTH + t;   // < 65536 float4
        float4 v = reinterpret_cast<const float4*>(WV)[i];
        uint16_t h0, h1, h2, h3, l0, l1, l2, l3;
        split_bf16(v.x, h0, l0); split_bf16(v.y, h1, l1);
        split_bf16(v.z, h2, l2); split_bf16(v.w, h3, l3);
        reinterpret_cast<uint2*>(g_Wvh)[i] =
            make_uint2((uint32_t)h0 | ((uint32_t)h1 << 16), (uint32_t)h2 | ((uint32_t)h3 << 16));
        reinterpret_cast<uint2*>(g_Wvl)[i] =
            make_uint2((uint32_t)l0 | ((uint32_t)l1 << 16), (uint32_t)l2 | ((uint32_t)l3 << 16));
        return;
    }

    // M gemm: 64 CTAs, 64x64 tile each
    const int mb = bid - 8448;
    const int e0 = (mb >> 3) * 64;
    const int d0 = (mb & 7) * 64;
    const int tx = t & 15, ty = t >> 4;

    float acc[4][4];
    #pragma unroll
    for (int a = 0; a < 4; a++)
        #pragma unroll
        for (int b = 0; b < 4; b++) acc[a][b] = 0.0f;

    for (int f0 = 0; f0 < DM; f0 += 32) {
        #pragma unroll
        for (int j = 0; j < 2; j++) {
            int idx = t + j * NTH;          // 512 float4 slots
            int row = idx >> 4, c4 = idx & 15;
            *reinterpret_cast<float4*>(&sa[row][c4 * 4]) =
                *reinterpret_cast<const float4*>(&WK[(size_t)(f0 + row) * DM + e0 + c4 * 4]);
            *reinterpret_cast<float4*>(&sb_[row][c4 * 4]) =
                *reinterpret_cast<const float4*>(&WQ[(size_t)(f0 + row) * DM + d0 + c4 * 4]);
        }
        __syncthreads();
        #pragma unroll
        for (int ff = 0; ff < 32; ff++) {
            float ra[4], rb[4];
            #pragma unroll
            for (int a = 0; a < 4; a++) ra[a] = sa[ff][ty * 4 + a];
            #pragma unroll
            for (int b = 0; b < 4; b++) rb[b] = sb_[ff][tx * 4 + b];
            #pragma unroll
            for (int a = 0; a < 4; a++)
                #pragma unroll
                for (int b = 0; b < 4; b++)
                    acc[a][b] += ra[a] * rb[b];
        }
        __syncthreads();
    }

    #pragma unroll
    for (int a = 0; a < 4; a++) {
        #pragma unroll
        for (int b = 0; b < 4; b++) {
            int e = e0 + ty * 4 + a;
            int d = d0 + tx * 4 + b;
            uint16_t h, l;
            split_bf16(acc[a][b] * SOFTMAX_SCALE, h, l);
            g_MTh[(size_t)e * DM + d] = __ushort_as_bfloat16(h);
            g_MTl[(size_t)e * DM + d] = __ushort_as_bfloat16(l);
        }
    }
}

// ---------------------------------------------------------------- kernel: projG (G = x*M)
__global__ __launch_bounds__(NTH, 2)
void projg_kernel() {
    extern __shared__ __align__(128) char smem[];
    const uint32_t sb = smem_u32(smem);
    const int t = threadIdx.x, wid = t >> 5, lane = t & 31;
    const int wr = wid & 3, wc = wid >> 2;
    const int m0 = blockIdx.y * BM;
    const int n0 = blockIdx.x * BN;

    float acc[2][8][4];
    #pragma unroll
    for (int a = 0; a < 2; a++)
        #pragma unroll
        for (int b = 0; b < 8; b++)
            #pragma unroll
            for (int r = 0; r < 4; r++) acc[a][b][r] = 0.0f;

    run_gemm(sb, t, wr, wc, lane,
             g_xh + (size_t)m0 * DM, g_xl + (size_t)m0 * DM,
             g_MTh + (size_t)n0 * DM, g_MTl + (size_t)n0 * DM,
             DM, DM, DM / BK, acc);

    #pragma unroll
    for (int mi = 0; mi < 2; mi++) {
        #pragma unroll
        for (int ni = 0; ni < 8; ni++) {
            int row = m0 + wr * 32 + mi * 16 + (lane >> 2);
            int col = n0 + wc * 64 + ni * 8 + ((lane & 3) << 1);
            uint16_t h0, h1, l0, l1;
            split_bf16(acc[mi][ni][0], h0, l0);
            split_bf16(acc[mi][ni][1], h1, l1);
            *reinterpret_cast<uint32_t*>(&g_Gh[(size_t)row * DM + col]) =
                (uint32_t)h0 | ((uint32_t)h1 << 16);
            *reinterpret_cast<uint32_t*>(&g_Gl[(size_t)row * DM + col]) =
                (uint32_t)l0 | ((uint32_t)l1 << 16);
            split_bf16(acc[mi][ni][2], h0, l0);
            split_bf16(acc[mi][ni][3], h1, l1);
            *reinterpret_cast<uint32_t*>(&g_Gh[(size_t)(row + 8) * DM + col]) =
                (uint32_t)h0 | ((uint32_t)h1 << 16);
            *reinterpret_cast<uint32_t*>(&g_Gl[(size_t)(row + 8) * DM + col]) =
                (uint32_t)l0 | ((uint32_t)l1 << 16);
        }
    }
}

// ---------------------------------------------------------------- kernel: scores + projV + prefill
// z in [0,4): scores batch z.  z == 4: idx = by*32+bx; idx<512 -> projV; else prefill.
__global__ __launch_bounds__(NTH, 2)
void scores_kernel(float* __restrict__ att, float* __restrict__ out,
                   const float* __restrict__ x) {
    extern __shared__ __align__(128) char smem[];
    const uint32_t sb = smem_u32(smem);
    const int t = threadIdx.x, wid = t >> 5, lane = t & 31;
    const int wr = wid & 3, wc = wid >> 2;

    if (blockIdx.z == 4) {
        const int idx = blockIdx.y * 32 + blockIdx.x;
        if (idx >= 512) {
            // prefill: out = x (residual base), 4096 float4 per CTA
            const int seg = idx - 512;
            #pragma unroll
            for (int r = 0; r < 16; r++) {
                int i = seg * 4096 + r * NTH + t;
                reinterpret_cast<float4*>(out)[i] = reinterpret_cast<const float4*>(x)[i];
            }
            return;
        }
        // projV: V = x * Wv^T, transposed split write
        const int n0 = (idx & 3) * BN;
        const int m0 = (idx >> 2) * BM;

        float acc[2][8][4];
        #pragma unroll
        for (int a = 0; a < 2; a++)
            #pragma unroll
            for (int c = 0; c < 8; c++)
                #pragma unroll
                for (int r = 0; r < 4; r++) acc[a][c][r] = 0.0f;

        run_gemm(sb, t, wr, wc, lane,
                 g_xh + (size_t)m0 * DM, g_xl + (size_t)m0 * DM,
                 g_Wvh + (size_t)n0 * DM, g_Wvl + (size_t)n0 * DM,
                 DM, DM, DM / BK, acc);

        __syncthreads();
        #pragma unroll
        for (int mi = 0; mi < 2; mi++) {
            #pragma unroll
            for (int ni = 0; ni < 8; ni++) {
                #pragma unroll
                for (int r = 0; r < 4; r++) {
                    int srow = wr * 32 + mi * 16 + (lane >> 2) + ((r >> 1) << 3);
                    int dcol = wc * 64 + ni * 8 + ((lane & 3) << 1) + (r & 1);
                    uint16_t h, l;
                    split_bf16(acc[mi][ni][r], h, l);
                    *reinterpret_cast<uint16_t*>(smem + dcol * 256 + srow * 2) = h;
                    *reinterpret_cast<uint16_t*>(smem + 32768 + dcol * 256 + srow * 2) = l;
                }
            }
        }
        __syncthreads();
        const int b = m0 >> 12, s0r = m0 & (SEQ - 1);
        const int d = t >> 1, half = t & 1;
        const uint4* sh = reinterpret_cast<const uint4*>(smem + d * 256 + half * 128);
        const uint4* sl = reinterpret_cast<const uint4*>(smem + 32768 + d * 256 + half * 128);
        size_t o = ((size_t)b * DM + n0 + d) * SEQ + s0r + half * 64;
        uint4* dh = reinterpret_cast<uint4*>(g_Vth + o);
        uint4* dl = reinterpret_cast<uint4*>(g_Vtl + o);
        #pragma unroll
        for (int q = 0; q < 8; q++) { dh[q] = sh[q]; dl[q] = sl[q]; }
        return;
    }

    // scores: S = G x^T
    const int kt = blockIdx.x, qt = blockIdx.y;
    const int b = blockIdx.z;
    float* __restrict__ attb = att + (size_t)b * SEQ * SEQ;

    if (kt > qt) {
        int row = qt * BM + (t >> 1);
        int col = kt * BN + (t & 1) * 64;
        float4 z = make_float4(0.f, 0.f, 0.f, 0.f);
        float4* dst = reinterpret_cast<float4*>(&attb[(size_t)row * SEQ + col]);
        #pragma unroll
        for (int i = 0; i < 16; i++) dst[i] = z;
        return;
    }

    const size_t qr = ((size_t)b * SEQ + qt * BM) * DM;
    const size_t kr = ((size_t)b * SEQ + kt * BN) * DM;

    float acc[2][8][4];
    #pragma unroll
    for (int a = 0; a < 2; a++)
        #pragma unroll
        for (int c = 0; c < 8; c++)
            #pragma unroll
            for (int r = 0; r < 4; r++) acc[a][c][r] = 0.0f;

    run_gemm(sb, t, wr, wc, lane,
             g_Gh + qr, g_Gl + qr, g_xh + kr, g_xl + kr,
             DM, DM, DM / BK, acc);

    #pragma unroll
    for (int mi = 0; mi < 2; mi++) {
        #pragma unroll
        for (int ni = 0; ni < 8; ni++) {
            int row = qt * BM + wr * 32 + mi * 16 + (lane >> 2);
            int col = kt * BN + wc * 64 + ni * 8 + ((lane & 3) << 1);
            *reinterpret_cast<float2*>(&attb[(size_t)row * SEQ + col]) =
                make_float2(acc[mi][ni][0], acc[mi][ni][1]);
            *reinterpret_cast<float2*>(&attb[(size_t)(row + 8) * SEQ + col]) =
                make_float2(acc[mi][ni][2], acc[mi][ni][3]);
        }
    }
}

// ---------------------------------------------------------------- kernel: softmax (vectorized)
__global__ __launch_bounds__(NTH)
void softmax_kernel(float* __restrict__ att) {
    const int rr = blockIdx.x;
    const int b = rr >> 12;
    const int q = rr & (SEQ - 1);
    float* __restrict__ row = att + (size_t)b * SEQ * SEQ + (size_t)q * SEQ;
    __nv_bfloat16* __restrict__ ph = g_Ph + (size_t)b * SEQ * SEQ + (size_t)q * SEQ;
    __nv_bfloat16* __restrict__ pl = g_Pl + (size_t)b * SEQ * SEQ + (size_t)q * SEQ;
    const int L = q + 1;
    const int L4 = (L + 3) >> 2;
    const int jmax4 = (((q >> 7) + 1) << 7) >> 2;   // pad to 128-tile, /4

    __shared__ float4 sm4[SEQ / 4];
    __shared__ float red[NTH];
    const int t = threadIdx.x;

    float mx = -INFINITY;
    for (int j4 = t; j4 < L4; j4 += NTH) {
        float4 v = reinterpret_cast<const float4*>(row)[j4];
        int base = j4 << 2;
        float m1 = (base + 1 < L) ? v.y : -INFINITY;
        float m2 = (base + 2 < L) ? v.z : -INFINITY;
        float m3 = (base + 3 < L) ? v.w : -INFINITY;
        mx = fmaxf(mx, fmaxf(fmaxf(v.x, m1), fmaxf(m2, m3)));
        sm4[j4] = v;
    }
    red[t] = mx;
    __syncthreads();
    #pragma unroll
    for (int s = NTH / 2; s > 0; s >>= 1) {
        if (t < s) red[t] = fmaxf(red[t], red[t + s]);
        __syncthreads();
    }
    const float rowmax = red[0];
    __syncthreads();

    float sum = 0.0f;
    for (int j4 = t; j4 < L4; j4 += NTH) {
        float4 v = sm4[j4];
        int base = j4 << 2;
        float e0 = __expf(v.x - rowmax);
        float e1 = (base + 1 < L) ? __expf(v.y - rowmax) : 0.0f;
        float e2 = (base + 2 < L) ? __expf(v.z - rowmax) : 0.0f;
        float e3 = (base + 3 < L) ? __expf(v.w - rowmax) : 0.0f;
        sm4[j4] = make_float4(e0, e1, e2, e3);
        sum += (e0 + e1) + (e2 + e3);
    }
    red[t] = sum;
    __syncthreads();
    #pragma unroll
    for (int s = NTH / 2; s > 0; s >>= 1) {
        if (t < s) red[t] += red[t + s];
        __syncthreads();
    }
    const float inv = 1.0f / red[0];

    for (int j4 = t; j4 < jmax4; j4 += NTH) {
        float4 v = (j4 < L4) ? sm4[j4] : make_float4(0.f, 0.f, 0.f, 0.f);
        float4 o = make_float4(v.x * inv, v.y * inv, v.z * inv, v.w * inv);
        reinterpret_cast<float4*>(row)[j4] = o;
        uint16_t h0, h1, h2, h3, l0, l1, l2, l3;
        split_bf16(o.x, h0, l0); split_bf16(o.y, h1, l1);
        split_bf16(o.z, h2, l2); split_bf16(o.w, h3, l3);
        reinterpret_cast<uint2*>(ph)[j4] =
            make_uint2((uint32_t)h0 | ((uint32_t)h1 << 16), (uint32_t)h2 | ((uint32_t)h3 << 16));
        reinterpret_cast<uint2*>(pl)[j4] =
            make_uint2((uint32_t)l0 | ((uint32_t)l1 << 16), (uint32_t)l2 | ((uint32_t)l3 << 16));
    }
}

// ---------------------------------------------------------------- kernel: AV split-K (atomic accumulate into out = x)
__global__ __launch_bounds__(NTH, 2)
void av_kernel(float* __restrict__ out) {
    const int b = blockIdx.z;
    const int qt = blockIdx.y >> 2;
    const int seg = blockIdx.y & 3;
    const int n0 = blockIdx.x * BN;
    const int m0 = qt * BM;              // batch-local q row

    const int nch = 4 * (qt + 1);        // total causal chunks for this q tile
    const int c0 = seg * 32;
    if (c0 >= nch) return;               // empty split
    const int nloc = min(32, nch - c0);

    extern __shared__ __align__(128) char smem[];
    const uint32_t sb = smem_u32(smem);
    const int t = threadIdx.x, wid = t >> 5, lane = t & 31;
    const int wr = wid & 3, wc = wid >> 2;

    const size_t pr = ((size_t)b * SEQ + m0) * SEQ + (size_t)c0 * BK;
    const size_t vr = ((size_t)b * DM + n0) * SEQ + (size_t)c0 * BK;

    float acc[2][8][4];
    #pragma unroll
    for (int a = 0; a < 2; a++)
        #pragma unroll
        for (int c = 0; c < 8; c++)
            #pragma unroll
            for (int r = 0; r < 4; r++) acc[a][c][r] = 0.0f;

    run_gemm(sb, t, wr, wc, lane,
             g_Ph + pr, g_Pl + pr, g_Vth + vr, g_Vtl + vr,
             SEQ, SEQ, nloc, acc);

    #pragma unroll
    for (int mi = 0; mi < 2; mi++) {
        #pragma unroll
        for (int ni = 0; ni < 8; ni++) {
            int row = m0 + wr * 32 + mi * 16 + (lane >> 2);
            int col = n0 + wc * 64 + ni * 8 + ((lane & 3) << 1);
            size_t base = ((size_t)b * SEQ + row) * DM + col;
            atomicAdd(&out[base],     acc[mi][ni][0]);
            atomicAdd(&out[base + 1], acc[mi][ni][1]);
            size_t base8 = base + (size_t)8 * DM;
            atomicAdd(&out[base8],     acc[mi][ni][2]);
            atomicAdd(&out[base8 + 1], acc[mi][ni][3]);
        }
    }
}

// ---------------------------------------------------------------- launch
extern "C" void kernel_launch(void* const* d_in, const int* in_sizes, int n_in,
                              void* d_out, int out_size) {
    const float* x  = (const float*)d_in[0];
    const float* WQ = (const float*)d_in[1];
    const float* WK = (const float*)d_in[2];
    const float* WV = (const float*)d_in[3];

    float* out = (float*)d_out;                   // [B,S,D]
    float* att = out + (size_t)BSZ * SEQ * DM;    // [B,S,S]

    cudaFuncSetAttribute(projg_kernel,  cudaFuncAttributeMaxDynamicSharedMemorySize, SMEM_TOTAL);
    cudaFuncSetAttribute(scores_kernel, cudaFuncAttributeMaxDynamicSharedMemorySize, SMEM_TOTAL);
    cudaFuncSetAttribute(av_kernel,     cudaFuncAttributeMaxDynamicSharedMemorySize, SMEM_TOTAL);

    // 1) prep: split x, split Wv, fp32 M = scale * Wk^T Wq (with hi/lo output)
    prep_kernel<<<8512, NTH>>>(x, WQ, WK, WV);

    // 2) G = x M (scale folded)
    projg_kernel<<<dim3(DM / BN, NROWS / BM), NTH, SMEM_TOTAL>>>();

    // 3) causal scores S = G x^T (+ zero-fill) | projV | prefill out = x
    scores_kernel<<<dim3(SEQ / BN, SEQ / BM, 5), NTH, SMEM_TOTAL>>>(att, out, x);

    // 4) softmax: fp32 probs to d_out, bf16 hi/lo probs to scratch
    softmax_kernel<<<NROWS, NTH>>>(att);

    // 5) O += P @ V  (split-K, 4 segments of <=32 chunks, atomic accumulate)
    av_kernel<<<dim3(DM / BN, (SEQ / BM) * 4, BSZ), NTH, SMEM_TOTAL>>>(out);
}

// round 13
// speedup vs baseline: 1.0236x; 1.0236x over previous
#include <cuda_runtime.h>
#include <cuda_bf16.h>
#include <math.h>
#include <stdint.h>

// ---------------------------------------------------------------- dims
#define BSZ 4
#define SEQ 4096
#define DM  512
#define NROWS (BSZ * SEQ)                 // 16384
#define NTH 256
#define BM 128
#define BN 128
#define BK 32
#define SOFTMAX_SCALE 0.04419417382415922f

// smem stage layout (bf16 tiles, 64-byte rows, SW64 swizzle)
// regions within a stage: AH 0, AL 8192, BH 16384, BL 24576
#define STAGE 32768
#define NSTAGE 3
#define SMEM_TOTAL (NSTAGE * STAGE)       // 98304 bytes -> 2 CTAs/SM

#define SW64(o) ((uint32_t)(o) ^ ((((uint32_t)(o)) >> 3) & 0x30u))

// ---------------------------------------------------------------- scratch
__device__ __nv_bfloat16 g_xh[(size_t)NROWS * DM];
__device__ __nv_bfloat16 g_xl[(size_t)NROWS * DM];
__device__ __nv_bfloat16 g_Wvh[DM * DM];    // Wv    [e][d]
__device__ __nv_bfloat16 g_Wvl[DM * DM];
__device__ __nv_bfloat16 g_MTh[DM * DM];    // (Wq^T Wk)^T * scale  [e][d]
__device__ __nv_bfloat16 g_MTl[DM * DM];
__device__ __nv_bfloat16 g_Gh[(size_t)NROWS * DM];   // G = x*M*scale
__device__ __nv_bfloat16 g_Gl[(size_t)NROWS * DM];
__device__ __nv_bfloat16 g_Vth[(size_t)BSZ * DM * SEQ];  // V^T [b][d][s]
__device__ __nv_bfloat16 g_Vtl[(size_t)BSZ * DM * SEQ];
__device__ __nv_bfloat16 g_Ph[(size_t)BSZ * SEQ * SEQ];  // probs hi/lo
__device__ __nv_bfloat16 g_Pl[(size_t)BSZ * SEQ * SEQ];

// ---------------------------------------------------------------- helpers
__device__ __forceinline__ uint32_t smem_u32(const void* p) {
    return (uint32_t)__cvta_generic_to_shared(p);
}
__device__ __forceinline__ void ldmx4(uint32_t r[4], uint32_t addr) {
    asm volatile("ldmatrix.sync.aligned.m8n8.x4.shared.b16 {%0,%1,%2,%3}, [%4];"
                 : "=r"(r[0]), "=r"(r[1]), "=r"(r[2]), "=r"(r[3]) : "r"(addr));
}
__device__ __forceinline__ void mma16816(float d[4], const uint32_t a[4],
                                         uint32_t b0, uint32_t b1) {
    asm volatile("mma.sync.aligned.m16n8k16.row.col.f32.bf16.bf16.f32 "
                 "{%0,%1,%2,%3}, {%4,%5,%6,%7}, {%8,%9}, {%0,%1,%2,%3};"
                 : "+f"(d[0]), "+f"(d[1]), "+f"(d[2]), "+f"(d[3])
                 : "r"(a[0]), "r"(a[1]), "r"(a[2]), "r"(a[3]), "r"(b0), "r"(b1));
}
__device__ __forceinline__ void cpasync16(uint32_t dst, const void* src) {
    asm volatile("cp.async.cg.shared.global [%0], [%1], 16;" :: "r"(dst), "l"(src));
}
#define CP_COMMIT() asm volatile("cp.async.commit_group;")
#define CP_WAIT(N)  asm volatile("cp.async.wait_group %0;" :: "n"(N))

__device__ __forceinline__ void split_bf16(float v, uint16_t& h, uint16_t& l) {
    __nv_bfloat16 hb = __float2bfloat16(v);
    float r = v - __bfloat162float(hb);
    h = __bfloat16_as_ushort(hb);
    l = __bfloat16_as_ushort(__float2bfloat16(r));
}

// ---------------------------------------------------------------- GEMM engine
__device__ __forceinline__ void run_gemm(
    uint32_t sb, int t, int wr, int wc, int lane,
    const __nv_bfloat16* Ah, const __nv_bfloat16* Al,
    const __nv_bfloat16* Bh, const __nv_bfloat16* Bl,
    size_t ldA, size_t ldB, int nch, float acc[2][8][4])
{
    const int lrow = t >> 2;
    const int lc8 = (t & 3) << 3;
    const uint32_t sdst = SW64((lrow << 6) + (lc8 << 1));
    const __nv_bfloat16* pAh = Ah + (size_t)lrow * ldA + lc8;
    const __nv_bfloat16* pAl = Al + (size_t)lrow * ldA + lc8;
    const __nv_bfloat16* pBh = Bh + (size_t)lrow * ldB + lc8;
    const __nv_bfloat16* pBl = Bl + (size_t)lrow * ldB + lc8;
    const size_t a64 = (size_t)64 * ldA;
    const size_t b64 = (size_t)64 * ldB;

    const uint32_t aoff = SW64(((wr * 32 + (lane & 15)) << 6) + (((lane >> 4) << 3) << 1));
    const uint32_t boff = SW64(((wc * 64 + ((lane >> 4) << 3) + (lane & 7)) << 6)
                               + ((((lane >> 3) & 1) << 3) << 1));

    uint32_t s0 = sb, s1 = sb + STAGE, s2 = sb + 2 * STAGE;

#define LOADC(d)                                                                  \
    do {                                                                          \
        cpasync16((d) + sdst,                 pAh);                               \
        cpasync16((d) + sdst + 4096,          pAh + a64);                         \
        cpasync16((d) + 8192 + sdst,          pAl);                               \
        cpasync16((d) + 8192 + sdst + 4096,   pAl + a64);                         \
        cpasync16((d) + 16384 + sdst,         pBh);                               \
        cpasync16((d) + 16384 + sdst + 4096,  pBh + b64);                         \
        cpasync16((d) + 24576 + sdst,         pBl);                               \
        cpasync16((d) + 24576 + sdst + 4096,  pBl + b64);                         \
        pAh += BK; pAl += BK; pBh += BK; pBl += BK;                               \
    } while (0)

    LOADC(s0);
    CP_COMMIT();
    if (nch > 1) LOADC(s1);
    CP_COMMIT();

    for (int c = 0; c < nch; c++) {
        CP_WAIT(1);
        __syncthreads();
        if (c + 2 < nch) LOADC(s2);
        CP_COMMIT();

        #pragma unroll
        for (int ks = 0; ks < 2; ks++) {
            const uint32_t ab = s0 + (aoff ^ (ks << 5));
            const uint32_t bb = s0 + 16384 + (boff ^ (ks << 5));
            uint32_t ah[2][4], al[2][4];
            ldmx4(ah[0], ab);
            ldmx4(ah[1], ab + 1024);
            ldmx4(al[0], ab + 8192);
            ldmx4(al[1], ab + 8192 + 1024);
            #pragma unroll
            for (int p = 0; p < 4; p++) {
                uint32_t bh[4], bl[4];
                ldmx4(bh, bb + p * 1024);
                ldmx4(bl, bb + 8192 + p * 1024);
                #pragma unroll
                for (int mi = 0; mi < 2; mi++) {
                    mma16816(acc[mi][2 * p],     ah[mi], bh[0], bh[1]);
                    mma16816(acc[mi][2 * p + 1], ah[mi], bh[2], bh[3]);
                    mma16816(acc[mi][2 * p],     ah[mi], bl[0], bl[1]);
                    mma16816(acc[mi][2 * p + 1], ah[mi], bl[2], bl[3]);
                    mma16816(acc[mi][2 * p],     al[mi], bh[0], bh[1]);
                    mma16816(acc[mi][2 * p + 1], al[mi], bh[2], bh[3]);
                }
            }
        }
        uint32_t tmp = s0; s0 = s1; s1 = s2; s2 = tmp;
    }
#undef LOADC
}

// ---------------------------------------------------------------- kernel: prep
// bid [0,64):      fp32 M gemm: MT[e][d] = scale * sum_f Wk[f][e] Wq[f][d]
//                  (issued FIRST so it overlaps the memory-bound splits)
// bid [64,320):    split Wv -> g_Wvh/g_Wvl
// bid [320,8512):  split x  -> g_xh/g_xl
__global__ __launch_bounds__(NTH)
void prep_kernel(const float* __restrict__ x, const float* __restrict__ WQ,
                 const float* __restrict__ WK, const float* __restrict__ WV) {
    __shared__ float sa[32][64];   // Wk chunk [f][e]
    __shared__ float sb_[32][64];  // Wq chunk [f][d]
    const int bid = blockIdx.x;
    const int t = threadIdx.x;

    if (bid >= 320) {
        int i = (bid - 320) * NTH + t;     // < 2097152 float4
        float4 v = reinterpret_cast<const float4*>(x)[i];
        uint16_t h0, h1, h2, h3, l0, l1, l2, l3;
        split_bf16(v.x, h0, l0); split_bf16(v.y, h1, l1);
        split_bf16(v.z, h2, l2); split_bf16(v.w, h3, l3);
        reinterpret_cast<uint2*>(g_xh)[i] =
            make_uint2((uint32_t)h0 | ((uint32_t)h1 << 16), (uint32_t)h2 | ((uint32_t)h3 << 16));
        reinterpret_cast<uint2*>(g_xl)[i] =
            make_uint2((uint32_t)l0 | ((uint32_t)l1 << 16), (uint32_t)l2 | ((uint32_t)l3 << 16));
        return;
    }
    if (bid >= 64) {
        int i = (bid - 64) * NTH + t;   // < 65536 float4
        float4 v = reinterpret_cast<const float4*>(WV)[i];
        uint16_t h0, h1, h2, h3, l0, l1, l2, l3;
        split_bf16(v.x, h0, l0); split_bf16(v.y, h1, l1);
        split_bf16(v.z, h2, l2); split_bf16(v.w, h3, l3);
        reinterpret_cast<uint2*>(g_Wvh)[i] =
            make_uint2((uint32_t)h0 | ((uint32_t)h1 << 16), (uint32_t)h2 | ((uint32_t)h3 << 16));
        reinterpret_cast<uint2*>(g_Wvl)[i] =
            make_uint2((uint32_t)l0 | ((uint32_t)l1 << 16), (uint32_t)l2 | ((uint32_t)l3 << 16));
        return;
    }

    // M gemm: 64 CTAs, 64x64 tile each (fp32, CUDA cores)
    const int mb = bid;
    const int e0 = (mb >> 3) * 64;
    const int d0 = (mb & 7) * 64;
    const int tx = t & 15, ty = t >> 4;

    float acc[4][4];
    #pragma unroll
    for (int a = 0; a < 4; a++)
        #pragma unroll
        for (int b = 0; b < 4; b++) acc[a][b] = 0.0f;

    for (int f0 = 0; f0 < DM; f0 += 32) {
        #pragma unroll
        for (int j = 0; j < 2; j++) {
            int idx = t + j * NTH;          // 512 float4 slots
            int row = idx >> 4, c4 = idx & 15;
            *reinterpret_cast<float4*>(&sa[row][c4 * 4]) =
                *reinterpret_cast<const float4*>(&WK[(size_t)(f0 + row) * DM + e0 + c4 * 4]);
            *reinterpret_cast<float4*>(&sb_[row][c4 * 4]) =
                *reinterpret_cast<const float4*>(&WQ[(size_t)(f0 + row) * DM + d0 + c4 * 4]);
        }
        __syncthreads();
        #pragma unroll
        for (int ff = 0; ff < 32; ff++) {
            float ra[4], rb[4];
            #pragma unroll
            for (int a = 0; a < 4; a++) ra[a] = sa[ff][ty * 4 + a];
            #pragma unroll
            for (int b = 0; b < 4; b++) rb[b] = sb_[ff][tx * 4 + b];
            #pragma unroll
            for (int a = 0; a < 4; a++)
                #pragma unroll
                for (int b = 0; b < 4; b++)
                    acc[a][b] += ra[a] * rb[b];
        }
        __syncthreads();
    }

    #pragma unroll
    for (int a = 0; a < 4; a++) {
        #pragma unroll
        for (int b = 0; b < 4; b++) {
            int e = e0 + ty * 4 + a;
            int d = d0 + tx * 4 + b;
            uint16_t h, l;
            split_bf16(acc[a][b] * SOFTMAX_SCALE, h, l);
            g_MTh[(size_t)e * DM + d] = __ushort_as_bfloat16(h);
            g_MTl[(size_t)e * DM + d] = __ushort_as_bfloat16(l);
        }
    }
}

// ---------------------------------------------------------------- kernel: projG (G = x*M)
__global__ __launch_bounds__(NTH, 2)
void projg_kernel() {
    extern __shared__ __align__(128) char smem[];
    const uint32_t sb = smem_u32(smem);
    const int t = threadIdx.x, wid = t >> 5, lane = t & 31;
    const int wr = wid & 3, wc = wid >> 2;
    const int m0 = blockIdx.y * BM;
    const int n0 = blockIdx.x * BN;

    float acc[2][8][4];
    #pragma unroll
    for (int a = 0; a < 2; a++)
        #pragma unroll
        for (int b = 0; b < 8; b++)
            #pragma unroll
            for (int r = 0; r < 4; r++) acc[a][b][r] = 0.0f;

    run_gemm(sb, t, wr, wc, lane,
             g_xh + (size_t)m0 * DM, g_xl + (size_t)m0 * DM,
             g_MTh + (size_t)n0 * DM, g_MTl + (size_t)n0 * DM,
             DM, DM, DM / BK, acc);

    #pragma unroll
    for (int mi = 0; mi < 2; mi++) {
        #pragma unroll
        for (int ni = 0; ni < 8; ni++) {
            int row = m0 + wr * 32 + mi * 16 + (lane >> 2);
            int col = n0 + wc * 64 + ni * 8 + ((lane & 3) << 1);
            uint16_t h0, h1, l0, l1;
            split_bf16(acc[mi][ni][0], h0, l0);
            split_bf16(acc[mi][ni][1], h1, l1);
            *reinterpret_cast<uint32_t*>(&g_Gh[(size_t)row * DM + col]) =
                (uint32_t)h0 | ((uint32_t)h1 << 16);
            *reinterpret_cast<uint32_t*>(&g_Gl[(size_t)row * DM + col]) =
                (uint32_t)l0 | ((uint32_t)l1 << 16);
            split_bf16(acc[mi][ni][2], h0, l0);
            split_bf16(acc[mi][ni][3], h1, l1);
            *reinterpret_cast<uint32_t*>(&g_Gh[(size_t)(row + 8) * DM + col]) =
                (uint32_t)h0 | ((uint32_t)h1 << 16);
            *reinterpret_cast<uint32_t*>(&g_Gl[(size_t)(row + 8) * DM + col]) =
                (uint32_t)l0 | ((uint32_t)l1 << 16);
        }
    }
}

// ---------------------------------------------------------------- kernel: scores + projV + prefill
// z == 0: aux slab — idx = by*32+bx; idx<512 -> projV; else prefill out = x.
// z in [1,5): scores batch (z-1).
__global__ __launch_bounds__(NTH, 2)
void scores_kernel(float* __restrict__ att, float* __restrict__ out,
                   const float* __restrict__ x) {
    extern __shared__ __align__(128) char smem[];
    const uint32_t sb = smem_u32(smem);
    const int t = threadIdx.x, wid = t >> 5, lane = t & 31;
    const int wr = wid & 3, wc = wid >> 2;

    if (blockIdx.z == 0) {
        const int idx = blockIdx.y * 32 + blockIdx.x;
        if (idx >= 512) {
            // prefill: out = x (residual base), 4096 float4 per CTA
            const int seg = idx - 512;
            #pragma unroll
            for (int r = 0; r < 16; r++) {
                int i = seg * 4096 + r * NTH + t;
                reinterpret_cast<float4*>(out)[i] = reinterpret_cast<const float4*>(x)[i];
            }
            return;
        }
        // projV: V = x * Wv^T, transposed split write
        const int n0 = (idx & 3) * BN;
        const int m0 = (idx >> 2) * BM;

        float acc[2][8][4];
        #pragma unroll
        for (int a = 0; a < 2; a++)
            #pragma unroll
            for (int c = 0; c < 8; c++)
                #pragma unroll
                for (int r = 0; r < 4; r++) acc[a][c][r] = 0.0f;

        run_gemm(sb, t, wr, wc, lane,
                 g_xh + (size_t)m0 * DM, g_xl + (size_t)m0 * DM,
                 g_Wvh + (size_t)n0 * DM, g_Wvl + (size_t)n0 * DM,
                 DM, DM, DM / BK, acc);

        __syncthreads();
        #pragma unroll
        for (int mi = 0; mi < 2; mi++) {
            #pragma unroll
            for (int ni = 0; ni < 8; ni++) {
                #pragma unroll
                for (int r = 0; r < 4; r++) {
                    int srow = wr * 32 + mi * 16 + (lane >> 2) + ((r >> 1) << 3);
                    int dcol = wc * 64 + ni * 8 + ((lane & 3) << 1) + (r & 1);
                    uint16_t h, l;
                    split_bf16(acc[mi][ni][r], h, l);
                    *reinterpret_cast<uint16_t*>(smem + dcol * 256 + srow * 2) = h;
                    *reinterpret_cast<uint16_t*>(smem + 32768 + dcol * 256 + srow * 2) = l;
                }
            }
        }
        __syncthreads();
        const int b = m0 >> 12, s0r = m0 & (SEQ - 1);
        const int d = t >> 1, half = t & 1;
        const uint4* sh = reinterpret_cast<const uint4*>(smem + d * 256 + half * 128);
        const uint4* sl = reinterpret_cast<const uint4*>(smem + 32768 + d * 256 + half * 128);
        size_t o = ((size_t)b * DM + n0 + d) * SEQ + s0r + half * 64;
        uint4* dh = reinterpret_cast<uint4*>(g_Vth + o);
        uint4* dl = reinterpret_cast<uint4*>(g_Vtl + o);
        #pragma unroll
        for (int q = 0; q < 8; q++) { dh[q] = sh[q]; dl[q] = sl[q]; }
        return;
    }

    // scores: S = G x^T
    const int kt = blockIdx.x, qt = blockIdx.y;
    const int b = blockIdx.z - 1;
    float* __restrict__ attb = att + (size_t)b * SEQ * SEQ;

    if (kt > qt) {
        int row = qt * BM + (t >> 1);
        int col = kt * BN + (t & 1) * 64;
        float4 z = make_float4(0.f, 0.f, 0.f, 0.f);
        float4* dst = reinterpret_cast<float4*>(&attb[(size_t)row * SEQ + col]);
        #pragma unroll
        for (int i = 0; i < 16; i++) dst[i] = z;
        return;
    }

    const size_t qr = ((size_t)b * SEQ + qt * BM) * DM;
    const size_t kr = ((size_t)b * SEQ + kt * BN) * DM;

    float acc[2][8][4];
    #pragma unroll
    for (int a = 0; a < 2; a++)
        #pragma unroll
        for (int c = 0; c < 8; c++)
            #pragma unroll
            for (int r = 0; r < 4; r++) acc[a][c][r] = 0.0f;

    run_gemm(sb, t, wr, wc, lane,
             g_Gh + qr, g_Gl + qr, g_xh + kr, g_xl + kr,
             DM, DM, DM / BK, acc);

    #pragma unroll
    for (int mi = 0; mi < 2; mi++) {
        #pragma unroll
        for (int ni = 0; ni < 8; ni++) {
            int row = qt * BM + wr * 32 + mi * 16 + (lane >> 2);
            int col = kt * BN + wc * 64 + ni * 8 + ((lane & 3) << 1);
            *reinterpret_cast<float2*>(&attb[(size_t)row * SEQ + col]) =
                make_float2(acc[mi][ni][0], acc[mi][ni][1]);
            *reinterpret_cast<float2*>(&attb[(size_t)(row + 8) * SEQ + col]) =
                make_float2(acc[mi][ni][2], acc[mi][ni][3]);
        }
    }
}

// ---------------------------------------------------------------- kernel: softmax (vectorized)
__global__ __launch_bounds__(NTH)
void softmax_kernel(float* __restrict__ att) {
    const int rr = blockIdx.x;
    const int b = rr >> 12;
    const int q = rr & (SEQ - 1);
    float* __restrict__ row = att + (size_t)b * SEQ * SEQ + (size_t)q * SEQ;
    __nv_bfloat16* __restrict__ ph = g_Ph + (size_t)b * SEQ * SEQ + (size_t)q * SEQ;
    __nv_bfloat16* __restrict__ pl = g_Pl + (size_t)b * SEQ * SEQ + (size_t)q * SEQ;
    const int L = q + 1;
    const int L4 = (L + 3) >> 2;
    const int jmax4 = (((q >> 7) + 1) << 7) >> 2;   // pad to 128-tile, /4

    __shared__ float4 sm4[SEQ / 4];
    __shared__ float red[NTH];
    const int t = threadIdx.x;

    float mx = -INFINITY;
    for (int j4 = t; j4 < L4; j4 += NTH) {
        float4 v = reinterpret_cast<const float4*>(row)[j4];
        int base = j4 << 2;
        float m1 = (base + 1 < L) ? v.y : -INFINITY;
        float m2 = (base + 2 < L) ? v.z : -INFINITY;
        float m3 = (base + 3 < L) ? v.w : -INFINITY;
        mx = fmaxf(mx, fmaxf(fmaxf(v.x, m1), fmaxf(m2, m3)));
        sm4[j4] = v;
    }
    red[t] = mx;
    __syncthreads();
    #pragma unroll
    for (int s = NTH / 2; s > 0; s >>= 1) {
        if (t < s) red[t] = fmaxf(red[t], red[t + s]);
        __syncthreads();
    }
    const float rowmax = red[0];
    __syncthreads();

    float sum = 0.0f;
    for (int j4 = t; j4 < L4; j4 += NTH) {
        float4 v = sm4[j4];
        int base = j4 << 2;
        float e0 = __expf(v.x - rowmax);
        float e1 = (base + 1 < L) ? __expf(v.y - rowmax) : 0.0f;
        float e2 = (base + 2 < L) ? __expf(v.z - rowmax) : 0.0f;
        float e3 = (base + 3 < L) ? __expf(v.w - rowmax) : 0.0f;
        sm4[j4] = make_float4(e0, e1, e2, e3);
        sum += (e0 + e1) + (e2 + e3);
    }
    red[t] = sum;
    __syncthreads();
    #pragma unroll
    for (int s = NTH / 2; s > 0; s >>= 1) {
        if (t < s) red[t] += red[t + s];
        __syncthreads();
    }
    const float inv = 1.0f / red[0];

    for (int j4 = t; j4 < jmax4; j4 += NTH) {
        float4 v = (j4 < L4) ? sm4[j4] : make_float4(0.f, 0.f, 0.f, 0.f);
        float4 o = make_float4(v.x * inv, v.y * inv, v.z * inv, v.w * inv);
        reinterpret_cast<float4*>(row)[j4] = o;
        uint16_t h0, h1, h2, h3, l0, l1, l2, l3;
        split_bf16(o.x, h0, l0); split_bf16(o.y, h1, l1);
        split_bf16(o.z, h2, l2); split_bf16(o.w, h3, l3);
        reinterpret_cast<uint2*>(ph)[j4] =
            make_uint2((uint32_t)h0 | ((uint32_t)h1 << 16), (uint32_t)h2 | ((uint32_t)h3 << 16));
        reinterpret_cast<uint2*>(pl)[j4] =
            make_uint2((uint32_t)l0 | ((uint32_t)l1 << 16), (uint32_t)l2 | ((uint32_t)l3 << 16));
    }
}

// ---------------------------------------------------------------- kernel: AV split-K (atomic accumulate into out = x)
__global__ __launch_bounds__(NTH, 2)
void av_kernel(float* __restrict__ out) {
    const int b = blockIdx.z;
    const int qt = blockIdx.y >> 2;
    const int seg = blockIdx.y & 3;
    const int n0 = blockIdx.x * BN;
    const int m0 = qt * BM;              // batch-local q row

    const int nch = 4 * (qt + 1);        // total causal chunks for this q tile
    const int c0 = seg * 32;
    if (c0 >= nch) return;               // empty split
    const int nloc = min(32, nch - c0);

    extern __shared__ __align__(128) char smem[];
    const uint32_t sb = smem_u32(smem);
    const int t = threadIdx.x, wid = t >> 5, lane = t & 31;
    const int wr = wid & 3, wc = wid >> 2;

    const size_t pr = ((size_t)b * SEQ + m0) * SEQ + (size_t)c0 * BK;
    const size_t vr = ((size_t)b * DM + n0) * SEQ + (size_t)c0 * BK;

    float acc[2][8][4];
    #pragma unroll
    for (int a = 0; a < 2; a++)
        #pragma unroll
        for (int c = 0; c < 8; c++)
            #pragma unroll
            for (int r = 0; r < 4; r++) acc[a][c][r] = 0.0f;

    run_gemm(sb, t, wr, wc, lane,
             g_Ph + pr, g_Pl + pr, g_Vth + vr, g_Vtl + vr,
             SEQ, SEQ, nloc, acc);

    #pragma unroll
    for (int mi = 0; mi < 2; mi++) {
        #pragma unroll
        for (int ni = 0; ni < 8; ni++) {
            int row = m0 + wr * 32 + mi * 16 + (lane >> 2);
            int col = n0 + wc * 64 + ni * 8 + ((lane & 3) << 1);
            size_t base = ((size_t)b * SEQ + row) * DM + col;
            atomicAdd(&out[base],     acc[mi][ni][0]);
            atomicAdd(&out[base + 1], acc[mi][ni][1]);
            size_t base8 = base + (size_t)8 * DM;
            atomicAdd(&out[base8],     acc[mi][ni][2]);
            atomicAdd(&out[base8 + 1], acc[mi][ni][3]);
        }
    }
}

// ---------------------------------------------------------------- launch
extern "C" void kernel_launch(void* const* d_in, const int* in_sizes, int n_in,
                              void* d_out, int out_size) {
    const float* x  = (const float*)d_in[0];
    const float* WQ = (const float*)d_in[1];
    const float* WK = (const float*)d_in[2];
    const float* WV = (const float*)d_in[3];

    float* out = (float*)d_out;                   // [B,S,D]
    float* att = out + (size_t)BSZ * SEQ * DM;    // [B,S,S]

    cudaFuncSetAttribute(projg_kernel,  cudaFuncAttributeMaxDynamicSharedMemorySize, SMEM_TOTAL);
    cudaFuncSetAttribute(scores_kernel, cudaFuncAttributeMaxDynamicSharedMemorySize, SMEM_TOTAL);
    cudaFuncSetAttribute(av_kernel,     cudaFuncAttributeMaxDynamicSharedMemorySize, SMEM_TOTAL);

    // 1) prep: fp32 M gemm FIRST (overlaps), then split Wv, split x
    prep_kernel<<<8512, NTH>>>(x, WQ, WK, WV);

    // 2) G = x M (scale folded)
    projg_kernel<<<dim3(DM / BN, NROWS / BM), NTH, SMEM_TOTAL>>>();

    // 3) aux slab (projV + prefill, z=0) | causal scores S = G x^T (z=1..4)
    scores_kernel<<<dim3(SEQ / BN, SEQ / BM, 5), NTH, SMEM_TOTAL>>>(att, out, x);

    // 4) softmax: fp32 probs to d_out, bf16 hi/lo probs to scratch
    softmax_kernel<<<NROWS, NTH>>>(att);

    // 5) O += P @ V  (split-K, 4 segments of <=32 chunks, atomic accumulate)
    av_kernel<<<dim3(DM / BN, (SEQ / BM) * 4, BSZ), NTH, SMEM_TOTAL>>>(out);
}

// round 14
// speedup vs baseline: 1.0360x; 1.0121x over previous
#include <cuda_runtime.h>
#include <cuda_bf16.h>
#include <math.h>
#include <stdint.h>

// ---------------------------------------------------------------- dims
#define BSZ 4
#define SEQ 4096
#define DM  512
#define NROWS (BSZ * SEQ)                 // 16384
#define NTH 256
#define BM 128
#define BN 128
#define BK 32
#define SOFTMAX_SCALE 0.04419417382415922f

// smem stage layout (bf16 tiles, 64-byte rows, SW64 swizzle)
// regions within a stage: AH 0, AL 8192, BH 16384, BL 24576
#define STAGE 32768
#define NSTAGE 3
#define SMEM_TOTAL (NSTAGE * STAGE)       // 98304 bytes -> 2 CTAs/SM

#define SW64(o) ((uint32_t)(o) ^ ((((uint32_t)(o)) >> 3) & 0x30u))

// ---------------------------------------------------------------- scratch
__device__ __nv_bfloat16 g_xh[(size_t)NROWS * DM];
__device__ __nv_bfloat16 g_xl[(size_t)NROWS * DM];
__device__ __nv_bfloat16 g_Wvh[DM * DM];    // Wv    [e][d]
__device__ __nv_bfloat16 g_Wvl[DM * DM];
__device__ __nv_bfloat16 g_MTh[DM * DM];    // (Wq^T Wk)^T * scale  [e][d]
__device__ __nv_bfloat16 g_MTl[DM * DM];
__device__ __nv_bfloat16 g_Gh[(size_t)NROWS * DM];   // G = x*M*scale
__device__ __nv_bfloat16 g_Gl[(size_t)NROWS * DM];
__device__ __nv_bfloat16 g_Vth[(size_t)BSZ * DM * SEQ];  // V^T [b][d][s]
__device__ __nv_bfloat16 g_Vtl[(size_t)BSZ * DM * SEQ];
__device__ __nv_bfloat16 g_Ph[(size_t)BSZ * SEQ * SEQ];  // probs hi/lo
__device__ __nv_bfloat16 g_Pl[(size_t)BSZ * SEQ * SEQ];

// ---------------------------------------------------------------- helpers
__device__ __forceinline__ uint32_t smem_u32(const void* p) {
    return (uint32_t)__cvta_generic_to_shared(p);
}
__device__ __forceinline__ void ldmx4(uint32_t r[4], uint32_t addr) {
    asm volatile("ldmatrix.sync.aligned.m8n8.x4.shared.b16 {%0,%1,%2,%3}, [%4];"
                 : "=r"(r[0]), "=r"(r[1]), "=r"(r[2]), "=r"(r[3]) : "r"(addr));
}
__device__ __forceinline__ void mma16816(float d[4], const uint32_t a[4],
                                         uint32_t b0, uint32_t b1) {
    asm volatile("mma.sync.aligned.m16n8k16.row.col.f32.bf16.bf16.f32 "
                 "{%0,%1,%2,%3}, {%4,%5,%6,%7}, {%8,%9}, {%0,%1,%2,%3};"
                 : "+f"(d[0]), "+f"(d[1]), "+f"(d[2]), "+f"(d[3])
                 : "r"(a[0]), "r"(a[1]), "r"(a[2]), "r"(a[3]), "r"(b0), "r"(b1));
}
__device__ __forceinline__ void cpasync16(uint32_t dst, const void* src) {
    asm volatile("cp.async.cg.shared.global [%0], [%1], 16;" :: "r"(dst), "l"(src));
}
#define CP_COMMIT() asm volatile("cp.async.commit_group;")
#define CP_WAIT(N)  asm volatile("cp.async.wait_group %0;" :: "n"(N))

__device__ __forceinline__ void split_bf16(float v, uint16_t& h, uint16_t& l) {
    __nv_bfloat16 hb = __float2bfloat16(v);
    float r = v - __bfloat162float(hb);
    h = __bfloat16_as_ushort(hb);
    l = __bfloat16_as_ushort(__float2bfloat16(r));
}

// pack two floats into bf16x2 (lo in low half, hi in high half), round-nearest
__device__ __forceinline__ uint32_t pack2_bf16(float lo, float hi) {
    uint32_t r;
    asm("cvt.rn.bf16x2.f32 %0, %1, %2;" : "=r"(r) : "f"(hi), "f"(lo));
    return r;
}

// ---------------------------------------------------------------- GEMM engine
// wactive=false: warp skips ldmatrix+mma (loads/syncs unchanged, acc stays 0).
__device__ __forceinline__ void run_gemm(
    uint32_t sb, int t, int wr, int wc, int lane,
    const __nv_bfloat16* Ah, const __nv_bfloat16* Al,
    const __nv_bfloat16* Bh, const __nv_bfloat16* Bl,
    size_t ldA, size_t ldB, int nch, float acc[2][8][4], bool wactive = true)
{
    const int lrow = t >> 2;
    const int lc8 = (t & 3) << 3;
    const uint32_t sdst = SW64((lrow << 6) + (lc8 << 1));
    const __nv_bfloat16* pAh = Ah + (size_t)lrow * ldA + lc8;
    const __nv_bfloat16* pAl = Al + (size_t)lrow * ldA + lc8;
    const __nv_bfloat16* pBh = Bh + (size_t)lrow * ldB + lc8;
    const __nv_bfloat16* pBl = Bl + (size_t)lrow * ldB + lc8;
    const size_t a64 = (size_t)64 * ldA;
    const size_t b64 = (size_t)64 * ldB;

    const uint32_t aoff = SW64(((wr * 32 + (lane & 15)) << 6) + (((lane >> 4) << 3) << 1));
    const uint32_t boff = SW64(((wc * 64 + ((lane >> 4) << 3) + (lane & 7)) << 6)
                               + ((((lane >> 3) & 1) << 3) << 1));

    uint32_t s0 = sb, s1 = sb + STAGE, s2 = sb + 2 * STAGE;

#define LOADC(d)                                                                  \
    do {                                                                          \
        cpasync16((d) + sdst,                 pAh);                               \
        cpasync16((d) + sdst + 4096,          pAh + a64);                         \
        cpasync16((d) + 8192 + sdst,          pAl);                               \
        cpasync16((d) + 8192 + sdst + 4096,   pAl + a64);                         \
        cpasync16((d) + 16384 + sdst,         pBh);                               \
        cpasync16((d) + 16384 + sdst + 4096,  pBh + b64);                         \
        cpasync16((d) + 24576 + sdst,         pBl);                               \
        cpasync16((d) + 24576 + sdst + 4096,  pBl + b64);                         \
        pAh += BK; pAl += BK; pBh += BK; pBl += BK;                               \
    } while (0)

    LOADC(s0);
    CP_COMMIT();
    if (nch > 1) LOADC(s1);
    CP_COMMIT();

    for (int c = 0; c < nch; c++) {
        CP_WAIT(1);
        __syncthreads();
        if (c + 2 < nch) LOADC(s2);
        CP_COMMIT();

        if (wactive) {
            #pragma unroll
            for (int ks = 0; ks < 2; ks++) {
                const uint32_t ab = s0 + (aoff ^ (ks << 5));
                const uint32_t bb = s0 + 16384 + (boff ^ (ks << 5));
                uint32_t ah[2][4], al[2][4];
                ldmx4(ah[0], ab);
                ldmx4(ah[1], ab + 1024);
                ldmx4(al[0], ab + 8192);
                ldmx4(al[1], ab + 8192 + 1024);
                #pragma unroll
                for (int p = 0; p < 4; p++) {
                    uint32_t bh[4], bl[4];
                    ldmx4(bh, bb + p * 1024);
                    ldmx4(bl, bb + 8192 + p * 1024);
                    #pragma unroll
                    for (int mi = 0; mi < 2; mi++) {
                        mma16816(acc[mi][2 * p],     ah[mi], bh[0], bh[1]);
                        mma16816(acc[mi][2 * p + 1], ah[mi], bh[2], bh[3]);
                        mma16816(acc[mi][2 * p],     ah[mi], bl[0], bl[1]);
                        mma16816(acc[mi][2 * p + 1], ah[mi], bl[2], bl[3]);
                        mma16816(acc[mi][2 * p],     al[mi], bh[0], bh[1]);
                        mma16816(acc[mi][2 * p + 1], al[mi], bh[2], bh[3]);
                    }
                }
            }
        }
        uint32_t tmp = s0; s0 = s1; s1 = s2; s2 = tmp;
    }
#undef LOADC
}

// ---------------------------------------------------------------- kernel: prep
// bid [0,64):      fp32 M gemm: MT[e][d] = scale * sum_f Wk[f][e] Wq[f][d]
// bid [64,320):    split Wv -> g_Wvh/g_Wvl
// bid [320,8512):  split x  -> g_xh/g_xl
__global__ __launch_bounds__(NTH)
void prep_kernel(const float* __restrict__ x, const float* __restrict__ WQ,
                 const float* __restrict__ WK, const float* __restrict__ WV) {
    __shared__ float sa[32][64];   // Wk chunk [f][e]
    __shared__ float sb_[32][64];  // Wq chunk [f][d]
    const int bid = blockIdx.x;
    const int t = threadIdx.x;

    if (bid >= 320) {
        int i = (bid - 320) * NTH + t;     // < 2097152 float4
        float4 v = reinterpret_cast<const float4*>(x)[i];
        uint16_t h0, h1, h2, h3, l0, l1, l2, l3;
        split_bf16(v.x, h0, l0); split_bf16(v.y, h1, l1);
        split_bf16(v.z, h2, l2); split_bf16(v.w, h3, l3);
        reinterpret_cast<uint2*>(g_xh)[i] =
            make_uint2((uint32_t)h0 | ((uint32_t)h1 << 16), (uint32_t)h2 | ((uint32_t)h3 << 16));
        reinterpret_cast<uint2*>(g_xl)[i] =
            make_uint2((uint32_t)l0 | ((uint32_t)l1 << 16), (uint32_t)l2 | ((uint32_t)l3 << 16));
        return;
    }
    if (bid >= 64) {
        int i = (bid - 64) * NTH + t;   // < 65536 float4
        float4 v = reinterpret_cast<const float4*>(WV)[i];
        uint16_t h0, h1, h2, h3, l0, l1, l2, l3;
        split_bf16(v.x, h0, l0); split_bf16(v.y, h1, l1);
        split_bf16(v.z, h2, l2); split_bf16(v.w, h3, l3);
        reinterpret_cast<uint2*>(g_Wvh)[i] =
            make_uint2((uint32_t)h0 | ((uint32_t)h1 << 16), (uint32_t)h2 | ((uint32_t)h3 << 16));
        reinterpret_cast<uint2*>(g_Wvl)[i] =
            make_uint2((uint32_t)l0 | ((uint32_t)l1 << 16), (uint32_t)l2 | ((uint32_t)l3 << 16));
        return;
    }

    // M gemm: 64 CTAs, 64x64 tile each (fp32, CUDA cores)
    const int mb = bid;
    const int e0 = (mb >> 3) * 64;
    const int d0 = (mb & 7) * 64;
    const int tx = t & 15, ty = t >> 4;

    float acc[4][4];
    #pragma unroll
    for (int a = 0; a < 4; a++)
        #pragma unroll
        for (int b = 0; b < 4; b++) acc[a][b] = 0.0f;

    for (int f0 = 0; f0 < DM; f0 += 32) {
        #pragma unroll
        for (int j = 0; j < 2; j++) {
            int idx = t + j * NTH;          // 512 float4 slots
            int row = idx >> 4, c4 = idx & 15;
            *reinterpret_cast<float4*>(&sa[row][c4 * 4]) =
                *reinterpret_cast<const float4*>(&WK[(size_t)(f0 + row) * DM + e0 + c4 * 4]);
            *reinterpret_cast<float4*>(&sb_[row][c4 * 4]) =
                *reinterpret_cast<const float4*>(&WQ[(size_t)(f0 + row) * DM + d0 + c4 * 4]);
        }
        __syncthreads();
        #pragma unroll
        for (int ff = 0; ff < 32; ff++) {
            float ra[4], rb[4];
            #pragma unroll
            for (int a = 0; a < 4; a++) ra[a] = sa[ff][ty * 4 + a];
            #pragma unroll
            for (int b = 0; b < 4; b++) rb[b] = sb_[ff][tx * 4 + b];
            #pragma unroll
            for (int a = 0; a < 4; a++)
                #pragma unroll
                for (int b = 0; b < 4; b++)
                    acc[a][b] += ra[a] * rb[b];
        }
        __syncthreads();
    }

    #pragma unroll
    for (int a = 0; a < 4; a++) {
        #pragma unroll
        for (int b = 0; b < 4; b++) {
            int e = e0 + ty * 4 + a;
            int d = d0 + tx * 4 + b;
            uint16_t h, l;
            split_bf16(acc[a][b] * SOFTMAX_SCALE, h, l);
            g_MTh[(size_t)e * DM + d] = __ushort_as_bfloat16(h);
            g_MTl[(size_t)e * DM + d] = __ushort_as_bfloat16(l);
        }
    }
}

// ---------------------------------------------------------------- kernel: projG (G = x*M)
__global__ __launch_bounds__(NTH, 2)
void projg_kernel() {
    extern __shared__ __align__(128) char smem[];
    const uint32_t sb = smem_u32(smem);
    const int t = threadIdx.x, wid = t >> 5, lane = t & 31;
    const int wr = wid & 3, wc = wid >> 2;
    const int m0 = blockIdx.y * BM;
    const int n0 = blockIdx.x * BN;

    float acc[2][8][4];
    #pragma unroll
    for (int a = 0; a < 2; a++)
        #pragma unroll
        for (int b = 0; b < 8; b++)
            #pragma unroll
            for (int r = 0; r < 4; r++) acc[a][b][r] = 0.0f;

    run_gemm(sb, t, wr, wc, lane,
             g_xh + (size_t)m0 * DM, g_xl + (size_t)m0 * DM,
             g_MTh + (size_t)n0 * DM, g_MTl + (size_t)n0 * DM,
             DM, DM, DM / BK, acc);

    #pragma unroll
    for (int mi = 0; mi < 2; mi++) {
        #pragma unroll
        for (int ni = 0; ni < 8; ni++) {
            int row = m0 + wr * 32 + mi * 16 + (lane >> 2);
            int col = n0 + wc * 64 + ni * 8 + ((lane & 3) << 1);
            uint16_t h0, h1, l0, l1;
            split_bf16(acc[mi][ni][0], h0, l0);
            split_bf16(acc[mi][ni][1], h1, l1);
            *reinterpret_cast<uint32_t*>(&g_Gh[(size_t)row * DM + col]) =
                (uint32_t)h0 | ((uint32_t)h1 << 16);
            *reinterpret_cast<uint32_t*>(&g_Gl[(size_t)row * DM + col]) =
                (uint32_t)l0 | ((uint32_t)l1 << 16);
            split_bf16(acc[mi][ni][2], h0, l0);
            split_bf16(acc[mi][ni][3], h1, l1);
            *reinterpret_cast<uint32_t*>(&g_Gh[(size_t)(row + 8) * DM + col]) =
                (uint32_t)h0 | ((uint32_t)h1 << 16);
            *reinterpret_cast<uint32_t*>(&g_Gl[(size_t)(row + 8) * DM + col]) =
                (uint32_t)l0 | ((uint32_t)l1 << 16);
        }
    }
}

// ---------------------------------------------------------------- kernel: scores + projV + prefill
// z == 0: aux slab — idx = by*32+bx; idx<512 -> projV; else prefill out = x.
// z in [1,5): scores batch (z-1).
__global__ __launch_bounds__(NTH, 2)
void scores_kernel(float* __restrict__ att, float* __restrict__ out,
                   const float* __restrict__ x) {
    extern __shared__ __align__(128) char smem[];
    const uint32_t sb = smem_u32(smem);
    const int t = threadIdx.x, wid = t >> 5, lane = t & 31;
    const int wr = wid & 3, wc = wid >> 2;

    if (blockIdx.z == 0) {
        const int idx = blockIdx.y * 32 + blockIdx.x;
        if (idx >= 512) {
            // prefill: out = x (residual base), 4096 float4 per CTA
            const int seg = idx - 512;
            #pragma unroll
            for (int r = 0; r < 16; r++) {
                int i = seg * 4096 + r * NTH + t;
                reinterpret_cast<float4*>(out)[i] = reinterpret_cast<const float4*>(x)[i];
            }
            return;
        }
        // projV: V = x * Wv^T, transposed split write
        const int n0 = (idx & 3) * BN;
        const int m0 = (idx >> 2) * BM;

        float acc[2][8][4];
        #pragma unroll
        for (int a = 0; a < 2; a++)
            #pragma unroll
            for (int c = 0; c < 8; c++)
                #pragma unroll
                for (int r = 0; r < 4; r++) acc[a][c][r] = 0.0f;

        run_gemm(sb, t, wr, wc, lane,
                 g_xh + (size_t)m0 * DM, g_xl + (size_t)m0 * DM,
                 g_Wvh + (size_t)n0 * DM, g_Wvl + (size_t)n0 * DM,
                 DM, DM, DM / BK, acc);

        __syncthreads();
        #pragma unroll
        for (int mi = 0; mi < 2; mi++) {
            #pragma unroll
            for (int ni = 0; ni < 8; ni++) {
                #pragma unroll
                for (int r = 0; r < 4; r++) {
                    int srow = wr * 32 + mi * 16 + (lane >> 2) + ((r >> 1) << 3);
                    int dcol = wc * 64 + ni * 8 + ((lane & 3) << 1) + (r & 1);
                    uint16_t h, l;
                    split_bf16(acc[mi][ni][r], h, l);
                    *reinterpret_cast<uint16_t*>(smem + dcol * 256 + srow * 2) = h;
                    *reinterpret_cast<uint16_t*>(smem + 32768 + dcol * 256 + srow * 2) = l;
                }
            }
        }
        __syncthreads();
        const int b = m0 >> 12, s0r = m0 & (SEQ - 1);
        const int d = t >> 1, half = t & 1;
        const uint4* sh = reinterpret_cast<const uint4*>(smem + d * 256 + half * 128);
        const uint4* sl = reinterpret_cast<const uint4*>(smem + 32768 + d * 256 + half * 128);
        size_t o = ((size_t)b * DM + n0 + d) * SEQ + s0r + half * 64;
        uint4* dh = reinterpret_cast<uint4*>(g_Vth + o);
        uint4* dl = reinterpret_cast<uint4*>(g_Vtl + o);
        #pragma unroll
        for (int q = 0; q < 8; q++) { dh[q] = sh[q]; dl[q] = sl[q]; }
        return;
    }

    // scores: S = G x^T
    const int kt = blockIdx.x, qt = blockIdx.y;
    const int b = blockIdx.z - 1;
    float* __restrict__ attb = att + (size_t)b * SEQ * SEQ;

    if (kt > qt) {
        int row = qt * BM + (t >> 1);
        int col = kt * BN + (t & 1) * 64;
        float4 z = make_float4(0.f, 0.f, 0.f, 0.f);
        float4* dst = reinterpret_cast<float4*>(&attb[(size_t)row * SEQ + col]);
        #pragma unroll
        for (int i = 0; i < 16; i++) dst[i] = z;
        return;
    }

    const size_t qr = ((size_t)b * SEQ + qt * BM) * DM;
    const size_t kr = ((size_t)b * SEQ + kt * BN) * DM;

    float acc[2][8][4];
    #pragma unroll
    for (int a = 0; a < 2; a++)
        #pragma unroll
        for (int c = 0; c < 8; c++)
            #pragma unroll
            for (int r = 0; r < 4; r++) acc[a][c][r] = 0.0f;

    // diagonal tile: warps covering cols entirely above the diagonal are masked
    const bool wactive = !(kt == qt && wc == 1 && wr < 2);

    run_gemm(sb, t, wr, wc, lane,
             g_Gh + qr, g_Gl + qr, g_xh + kr, g_xl + kr,
             DM, DM, DM / BK, acc, wactive);

    #pragma unroll
    for (int mi = 0; mi < 2; mi++) {
        #pragma unroll
        for (int ni = 0; ni < 8; ni++) {
            int row = qt * BM + wr * 32 + mi * 16 + (lane >> 2);
            int col = kt * BN + wc * 64 + ni * 8 + ((lane & 3) << 1);
            *reinterpret_cast<float2*>(&attb[(size_t)row * SEQ + col]) =
                make_float2(acc[mi][ni][0], acc[mi][ni][1]);
            *reinterpret_cast<float2*>(&attb[(size_t)(row + 8) * SEQ + col]) =
                make_float2(acc[mi][ni][2], acc[mi][ni][3]);
        }
    }
}

// ---------------------------------------------------------------- kernel: softmax (vectorized, packed cvt)
__global__ __launch_bounds__(NTH, 8)
void softmax_kernel(float* __restrict__ att) {
    const int rr = blockIdx.x;
    const int b = rr >> 12;
    const int q = rr & (SEQ - 1);
    float* __restrict__ row = att + (size_t)b * SEQ * SEQ + (size_t)q * SEQ;
    __nv_bfloat16* __restrict__ ph = g_Ph + (size_t)b * SEQ * SEQ + (size_t)q * SEQ;
    __nv_bfloat16* __restrict__ pl = g_Pl + (size_t)b * SEQ * SEQ + (size_t)q * SEQ;
    const int L = q + 1;
    const int L4 = (L + 3) >> 2;
    const int jmax4 = (((q >> 7) + 1) << 7) >> 2;   // pad to 128-tile, /4

    __shared__ float4 sm4[SEQ / 4];
    __shared__ float red[NTH];
    const int t = threadIdx.x;

    float mx = -INFINITY;
    for (int j4 = t; j4 < L4; j4 += NTH) {
        float4 v = reinterpret_cast<const float4*>(row)[j4];
        int base = j4 << 2;
        float m1 = (base + 1 < L) ? v.y : -INFINITY;
        float m2 = (base + 2 < L) ? v.z : -INFINITY;
        float m3 = (base + 3 < L) ? v.w : -INFINITY;
        mx = fmaxf(mx, fmaxf(fmaxf(v.x, m1), fmaxf(m2, m3)));
        sm4[j4] = v;
    }
    red[t] = mx;
    __syncthreads();
    #pragma unroll
    for (int s = NTH / 2; s > 0; s >>= 1) {
        if (t < s) red[t] = fmaxf(red[t], red[t + s]);
        __syncthreads();
    }
    const float rowmax = red[0];
    __syncthreads();

    float sum = 0.0f;
    for (int j4 = t; j4 < L4; j4 += NTH) {
        float4 v = sm4[j4];
        int base = j4 << 2;
        float e0 = __expf(v.x - rowmax);
        float e1 = (base + 1 < L) ? __expf(v.y - rowmax) : 0.0f;
        float e2 = (base + 2 < L) ? __expf(v.z - rowmax) : 0.0f;
        float e3 = (base + 3 < L) ? __expf(v.w - rowmax) : 0.0f;
        sm4[j4] = make_float4(e0, e1, e2, e3);
        sum += (e0 + e1) + (e2 + e3);
    }
    red[t] = sum;
    __syncthreads();
    #pragma unroll
    for (int s = NTH / 2; s > 0; s >>= 1) {
        if (t < s) red[t] += red[t + s];
        __syncthreads();
    }
    const float inv = 1.0f / red[0];

    for (int j4 = t; j4 < jmax4; j4 += NTH) {
        float4 v = (j4 < L4) ? sm4[j4] : make_float4(0.f, 0.f, 0.f, 0.f);
        float4 o = make_float4(v.x * inv, v.y * inv, v.z * inv, v.w * inv);
        reinterpret_cast<float4*>(row)[j4] = o;
        // packed bf16x3 split: hi via one cvt per pair, lo via bit-reconstructed residual
        uint32_t h01 = pack2_bf16(o.x, o.y);
        uint32_t h23 = pack2_bf16(o.z, o.w);
        float r0 = o.x - __uint_as_float(h01 << 16);
        float r1 = o.y - __uint_as_float(h01 & 0xFFFF0000u);
        float r2 = o.z - __uint_as_float(h23 << 16);
        float r3 = o.w - __uint_as_float(h23 & 0xFFFF0000u);
        uint32_t l01 = pack2_bf16(r0, r1);
        uint32_t l23 = pack2_bf16(r2, r3);
        reinterpret_cast<uint2*>(ph)[j4] = make_uint2(h01, h23);
        reinterpret_cast<uint2*>(pl)[j4] = make_uint2(l01, l23);
    }
}

// ---------------------------------------------------------------- kernel: AV split-K (atomic accumulate into out = x)
__global__ __launch_bounds__(NTH, 2)
void av_kernel(float* __restrict__ out) {
    const int b = blockIdx.z;
    const int qt = blockIdx.y >> 2;
    const int seg = blockIdx.y & 3;
    const int n0 = blockIdx.x * BN;
    const int m0 = qt * BM;              // batch-local q row

    const int nch = 4 * (qt + 1);        // total causal chunks for this q tile
    const int c0 = seg * 32;
    if (c0 >= nch) return;               // empty split
    const int nloc = min(32, nch - c0);

    extern __shared__ __align__(128) char smem[];
    const uint32_t sb = smem_u32(smem);
    const int t = threadIdx.x, wid = t >> 5, lane = t & 31;
    const int wr = wid & 3, wc = wid >> 2;

    const size_t pr = ((size_t)b * SEQ + m0) * SEQ + (size_t)c0 * BK;
    const size_t vr = ((size_t)b * DM + n0) * SEQ + (size_t)c0 * BK;

    float acc[2][8][4];
    #pragma unroll
    for (int a = 0; a < 2; a++)
        #pragma unroll
        for (int c = 0; c < 8; c++)
            #pragma unroll
            for (int r = 0; r < 4; r++) acc[a][c][r] = 0.0f;

    run_gemm(sb, t, wr, wc, lane,
             g_Ph + pr, g_Pl + pr, g_Vth + vr, g_Vtl + vr,
             SEQ, SEQ, nloc, acc);

    #pragma unroll
    for (int mi = 0; mi < 2; mi++) {
        #pragma unroll
        for (int ni = 0; ni < 8; ni++) {
            int row = m0 + wr * 32 + mi * 16 + (lane >> 2);
            int col = n0 + wc * 64 + ni * 8 + ((lane & 3) << 1);
            size_t base = ((size_t)b * SEQ + row) * DM + col;
            atomicAdd(&out[base],     acc[mi][ni][0]);
            atomicAdd(&out[base + 1], acc[mi][ni][1]);
            size_t base8 = base + (size_t)8 * DM;
            atomicAdd(&out[base8],     acc[mi][ni][2]);
            atomicAdd(&out[base8 + 1], acc[mi][ni][3]);
        }
    }
}

// ---------------------------------------------------------------- launch
extern "C" void kernel_launch(void* const* d_in, const int* in_sizes, int n_in,
                              void* d_out, int out_size) {
    const float* x  = (const float*)d_in[0];
    const float* WQ = (const float*)d_in[1];
    const float* WK = (const float*)d_in[2];
    const float* WV = (const float*)d_in[3];

    float* out = (float*)d_out;                   // [B,S,D]
    float* att = out + (size_t)BSZ * SEQ * DM;    // [B,S,S]

    cudaFuncSetAttribute(projg_kernel,  cudaFuncAttributeMaxDynamicSharedMemorySize, SMEM_TOTAL);
    cudaFuncSetAttribute(scores_kernel, cudaFuncAttributeMaxDynamicSharedMemorySize, SMEM_TOTAL);
    cudaFuncSetAttribute(av_kernel,     cudaFuncAttributeMaxDynamicSharedMemorySize, SMEM_TOTAL);

    // 1) prep: fp32 M gemm FIRST (overlaps), then split Wv, split x
    prep_kernel<<<8512, NTH>>>(x, WQ, WK, WV);

    // 2) G = x M (scale folded)
    projg_kernel<<<dim3(DM / BN, NROWS / BM), NTH, SMEM_TOTAL>>>();

    // 3) aux slab (projV + prefill, z=0) | causal scores S = G x^T (z=1..4)
    scores_kernel<<<dim3(SEQ / BN, SEQ / BM, 5), NTH, SMEM_TOTAL>>>(att, out, x);

    // 4) softmax: fp32 probs to d_out, bf16 hi/lo probs to scratch
    softmax_kernel<<<NROWS, NTH>>>(att);

    // 5) O += P @ V  (split-K, 4 segments of <=32 chunks, atomic accumulate)
    av_kernel<<<dim3(DM / BN, (SEQ / BM) * 4, BSZ), NTH, SMEM_TOTAL>>>(out);
}

// round 15
// speedup vs baseline: 1.1411x; 1.1015x over previous
#include <cuda_runtime.h>
#include <cuda_bf16.h>
#include <math.h>
#include <stdint.h>

// ---------------------------------------------------------------- dims
#define BSZ 4
#define SEQ 4096
#define DM  512
#define NROWS (BSZ * SEQ)                 // 16384
#define NTH 256
#define BM 128
#define BN 128
#define BK 32
#define SOFTMAX_SCALE 0.04419417382415922f

// smem stage layout (bf16 tiles, 64-byte rows, SW64 swizzle)
// regions within a stage: AH 0, AL 8192, BH 16384, BL 24576
#define STAGE 32768
#define NSTAGE 3
#define SMEM_TOTAL (NSTAGE * STAGE)       // 98304 bytes -> 2 CTAs/SM

#define SW64(o) ((uint32_t)(o) ^ ((((uint32_t)(o)) >> 3) & 0x30u))

// ---------------------------------------------------------------- scratch
__device__ __nv_bfloat16 g_xh[(size_t)NROWS * DM];
__device__ __nv_bfloat16 g_xl[(size_t)NROWS * DM];
__device__ __nv_bfloat16 g_Wvh[DM * DM];    // Wv    [e][d]
__device__ __nv_bfloat16 g_Wvl[DM * DM];
__device__ __nv_bfloat16 g_MTh[DM * DM];    // (Wq^T Wk)^T * scale  [e][d]
__device__ __nv_bfloat16 g_MTl[DM * DM];
__device__ __nv_bfloat16 g_Gh[(size_t)NROWS * DM];   // G = x*M*scale
__device__ __nv_bfloat16 g_Gl[(size_t)NROWS * DM];
__device__ __nv_bfloat16 g_Vth[(size_t)BSZ * DM * SEQ];  // V^T [b][d][s]
__device__ __nv_bfloat16 g_Vtl[(size_t)BSZ * DM * SEQ];
__device__ __nv_bfloat16 g_Ph[(size_t)BSZ * SEQ * SEQ];  // probs hi only

// ---------------------------------------------------------------- helpers
__device__ __forceinline__ uint32_t smem_u32(const void* p) {
    return (uint32_t)__cvta_generic_to_shared(p);
}
__device__ __forceinline__ void ldmx4(uint32_t r[4], uint32_t addr) {
    asm volatile("ldmatrix.sync.aligned.m8n8.x4.shared.b16 {%0,%1,%2,%3}, [%4];"
                 : "=r"(r[0]), "=r"(r[1]), "=r"(r[2]), "=r"(r[3]) : "r"(addr));
}
__device__ __forceinline__ void mma16816(float d[4], const uint32_t a[4],
                                         uint32_t b0, uint32_t b1) {
    asm volatile("mma.sync.aligned.m16n8k16.row.col.f32.bf16.bf16.f32 "
                 "{%0,%1,%2,%3}, {%4,%5,%6,%7}, {%8,%9}, {%0,%1,%2,%3};"
                 : "+f"(d[0]), "+f"(d[1]), "+f"(d[2]), "+f"(d[3])
                 : "r"(a[0]), "r"(a[1]), "r"(a[2]), "r"(a[3]), "r"(b0), "r"(b1));
}
__device__ __forceinline__ void cpasync16(uint32_t dst, const void* src) {
    asm volatile("cp.async.cg.shared.global [%0], [%1], 16;" :: "r"(dst), "l"(src));
}
#define CP_COMMIT() asm volatile("cp.async.commit_group;")
#define CP_WAIT(N)  asm volatile("cp.async.wait_group %0;" :: "n"(N))

__device__ __forceinline__ void split_bf16(float v, uint16_t& h, uint16_t& l) {
    __nv_bfloat16 hb = __float2bfloat16(v);
    float r = v - __bfloat162float(hb);
    h = __bfloat16_as_ushort(hb);
    l = __bfloat16_as_ushort(__float2bfloat16(r));
}

// pack two floats into bf16x2 (lo arg -> low half), round-nearest
__device__ __forceinline__ uint32_t pack2_bf16(float lo, float hi) {
    uint32_t r;
    asm("cvt.rn.bf16x2.f32 %0, %1, %2;" : "=r"(r) : "f"(hi), "f"(lo));
    return r;
}

// ---------------------------------------------------------------- GEMM engine
// ALON=true : acc += Ah*Bh + Ah*Bl + Al*Bh   (full bf16x3 compensation)
// ALON=false: acc += Ah*Bh + Ah*Bl           (A is single bf16; AL region unused)
// wactive=false: warp skips ldmatrix+mma (loads/syncs unchanged, acc stays 0).
template <bool ALON>
__device__ __forceinline__ void run_gemm(
    uint32_t sb, int t, int wr, int wc, int lane,
    const __nv_bfloat16* Ah, const __nv_bfloat16* Al,
    const __nv_bfloat16* Bh, const __nv_bfloat16* Bl,
    size_t ldA, size_t ldB, int nch, float acc[2][8][4], bool wactive = true)
{
    const int lrow = t >> 2;
    const int lc8 = (t & 3) << 3;
    const uint32_t sdst = SW64((lrow << 6) + (lc8 << 1));
    const __nv_bfloat16* pAh = Ah + (size_t)lrow * ldA + lc8;
    const __nv_bfloat16* pAl = ALON ? (Al + (size_t)lrow * ldA + lc8) : pAh;
    const __nv_bfloat16* pBh = Bh + (size_t)lrow * ldB + lc8;
    const __nv_bfloat16* pBl = Bl + (size_t)lrow * ldB + lc8;
    const size_t a64 = (size_t)64 * ldA;
    const size_t b64 = (size_t)64 * ldB;

    const uint32_t aoff = SW64(((wr * 32 + (lane & 15)) << 6) + (((lane >> 4) << 3) << 1));
    const uint32_t boff = SW64(((wc * 64 + ((lane >> 4) << 3) + (lane & 7)) << 6)
                               + ((((lane >> 3) & 1) << 3) << 1));

    uint32_t s0 = sb, s1 = sb + STAGE, s2 = sb + 2 * STAGE;

    auto loadc = [&](uint32_t d) {
        cpasync16(d + sdst,                pAh);
        cpasync16(d + sdst + 4096,         pAh + a64);
        if (ALON) {
            cpasync16(d + 8192 + sdst,        pAl);
            cpasync16(d + 8192 + sdst + 4096, pAl + a64);
        }
        cpasync16(d + 16384 + sdst,        pBh);
        cpasync16(d + 16384 + sdst + 4096, pBh + b64);
        cpasync16(d + 24576 + sdst,        pBl);
        cpasync16(d + 24576 + sdst + 4096, pBl + b64);
        pAh += BK; pBh += BK; pBl += BK;
        if (ALON) pAl += BK;
    };

    loadc(s0);
    CP_COMMIT();
    if (nch > 1) loadc(s1);
    CP_COMMIT();

    for (int c = 0; c < nch; c++) {
        CP_WAIT(1);
        __syncthreads();
        if (c + 2 < nch) loadc(s2);
        CP_COMMIT();

        if (wactive) {
            #pragma unroll
            for (int ks = 0; ks < 2; ks++) {
                const uint32_t ab = s0 + (aoff ^ (ks << 5));
                const uint32_t bb = s0 + 16384 + (boff ^ (ks << 5));
                uint32_t ah[2][4], al[2][4];
                ldmx4(ah[0], ab);
                ldmx4(ah[1], ab + 1024);
                if (ALON) {
                    ldmx4(al[0], ab + 8192);
                    ldmx4(al[1], ab + 8192 + 1024);
                }
                #pragma unroll
                for (int p = 0; p < 4; p++) {
                    uint32_t bh[4], bl[4];
                    ldmx4(bh, bb + p * 1024);
                    ldmx4(bl, bb + 8192 + p * 1024);
                    #pragma unroll
                    for (int mi = 0; mi < 2; mi++) {
                        mma16816(acc[mi][2 * p],     ah[mi], bh[0], bh[1]);
                        mma16816(acc[mi][2 * p + 1], ah[mi], bh[2], bh[3]);
                        mma16816(acc[mi][2 * p],     ah[mi], bl[0], bl[1]);
                        mma16816(acc[mi][2 * p + 1], ah[mi], bl[2], bl[3]);
                        if (ALON) {
                            mma16816(acc[mi][2 * p],     al[mi], bh[0], bh[1]);
                            mma16816(acc[mi][2 * p + 1], al[mi], bh[2], bh[3]);
                        }
                    }
                }
            }
        }
        uint32_t tmp = s0; s0 = s1; s1 = s2; s2 = tmp;
    }
}

// ---------------------------------------------------------------- kernel: prep
// bid [0,64):      fp32 M gemm: MT[e][d] = scale * sum_f Wk[f][e] Wq[f][d]
// bid [64,320):    split Wv -> g_Wvh/g_Wvl
// bid [320,8512):  split x  -> g_xh/g_xl
__global__ __launch_bounds__(NTH)
void prep_kernel(const float* __restrict__ x, const float* __restrict__ WQ,
                 const float* __restrict__ WK, const float* __restrict__ WV) {
    __shared__ float sa[32][64];   // Wk chunk [f][e]
    __shared__ float sb_[32][64];  // Wq chunk [f][d]
    const int bid = blockIdx.x;
    const int t = threadIdx.x;

    if (bid >= 320) {
        int i = (bid - 320) * NTH + t;     // < 2097152 float4
        float4 v = reinterpret_cast<const float4*>(x)[i];
        uint16_t h0, h1, h2, h3, l0, l1, l2, l3;
        split_bf16(v.x, h0, l0); split_bf16(v.y, h1, l1);
        split_bf16(v.z, h2, l2); split_bf16(v.w, h3, l3);
        reinterpret_cast<uint2*>(g_xh)[i] =
            make_uint2((uint32_t)h0 | ((uint32_t)h1 << 16), (uint32_t)h2 | ((uint32_t)h3 << 16));
        reinterpret_cast<uint2*>(g_xl)[i] =
            make_uint2((uint32_t)l0 | ((uint32_t)l1 << 16), (uint32_t)l2 | ((uint32_t)l3 << 16));
        return;
    }
    if (bid >= 64) {
        int i = (bid - 64) * NTH + t;   // < 65536 float4
        float4 v = reinterpret_cast<const float4*>(WV)[i];
        uint16_t h0, h1, h2, h3, l0, l1, l2, l3;
        split_bf16(v.x, h0, l0); split_bf16(v.y, h1, l1);
        split_bf16(v.z, h2, l2); split_bf16(v.w, h3, l3);
        reinterpret_cast<uint2*>(g_Wvh)[i] =
            make_uint2((uint32_t)h0 | ((uint32_t)h1 << 16), (uint32_t)h2 | ((uint32_t)h3 << 16));
        reinterpret_cast<uint2*>(g_Wvl)[i] =
            make_uint2((uint32_t)l0 | ((uint32_t)l1 << 16), (uint32_t)l2 | ((uint32_t)l3 << 16));
        return;
    }

    // M gemm: 64 CTAs, 64x64 tile each (fp32, CUDA cores)
    const int mb = bid;
    const int e0 = (mb >> 3) * 64;
    const int d0 = (mb & 7) * 64;
    const int tx = t & 15, ty = t >> 4;

    float acc[4][4];
    #pragma unroll
    for (int a = 0; a < 4; a++)
        #pragma unroll
        for (int b = 0; b < 4; b++) acc[a][b] = 0.0f;

    for (int f0 = 0; f0 < DM; f0 += 32) {
        #pragma unroll
        for (int j = 0; j < 2; j++) {
            int idx = t + j * NTH;          // 512 float4 slots
            int row = idx >> 4, c4 = idx & 15;
            *reinterpret_cast<float4*>(&sa[row][c4 * 4]) =
                *reinterpret_cast<const float4*>(&WK[(size_t)(f0 + row) * DM + e0 + c4 * 4]);
            *reinterpret_cast<float4*>(&sb_[row][c4 * 4]) =
                *reinterpret_cast<const float4*>(&WQ[(size_t)(f0 + row) * DM + d0 + c4 * 4]);
        }
        __syncthreads();
        #pragma unroll
        for (int ff = 0; ff < 32; ff++) {
            float ra[4], rb[4];
            #pragma unroll
            for (int a = 0; a < 4; a++) ra[a] = sa[ff][ty * 4 + a];
            #pragma unroll
            for (int b = 0; b < 4; b++) rb[b] = sb_[ff][tx * 4 + b];
            #pragma unroll
            for (int a = 0; a < 4; a++)
                #pragma unroll
                for (int b = 0; b < 4; b++)
                    acc[a][b] += ra[a] * rb[b];
        }
        __syncthreads();
    }

    #pragma unroll
    for (int a = 0; a < 4; a++) {
        #pragma unroll
        for (int b = 0; b < 4; b++) {
            int e = e0 + ty * 4 + a;
            int d = d0 + tx * 4 + b;
            uint16_t h, l;
            split_bf16(acc[a][b] * SOFTMAX_SCALE, h, l);
            g_MTh[(size_t)e * DM + d] = __ushort_as_bfloat16(h);
            g_MTl[(size_t)e * DM + d] = __ushort_as_bfloat16(l);
        }
    }
}

// ---------------------------------------------------------------- kernel: projG (G = x*M)
__global__ __launch_bounds__(NTH, 2)
void projg_kernel() {
    extern __shared__ __align__(128) char smem[];
    const uint32_t sb = smem_u32(smem);
    const int t = threadIdx.x, wid = t >> 5, lane = t & 31;
    const int wr = wid & 3, wc = wid >> 2;
    const int m0 = blockIdx.y * BM;
    const int n0 = blockIdx.x * BN;

    float acc[2][8][4];
    #pragma unroll
    for (int a = 0; a < 2; a++)
        #pragma unroll
        for (int b = 0; b < 8; b++)
            #pragma unroll
            for (int r = 0; r < 4; r++) acc[a][b][r] = 0.0f;

    run_gemm<true>(sb, t, wr, wc, lane,
                   g_xh + (size_t)m0 * DM, g_xl + (size_t)m0 * DM,
                   g_MTh + (size_t)n0 * DM, g_MTl + (size_t)n0 * DM,
                   DM, DM, DM / BK, acc);

    #pragma unroll
    for (int mi = 0; mi < 2; mi++) {
        #pragma unroll
        for (int ni = 0; ni < 8; ni++) {
            int row = m0 + wr * 32 + mi * 16 + (lane >> 2);
            int col = n0 + wc * 64 + ni * 8 + ((lane & 3) << 1);
            uint16_t h0, h1, l0, l1;
            split_bf16(acc[mi][ni][0], h0, l0);
            split_bf16(acc[mi][ni][1], h1, l1);
            *reinterpret_cast<uint32_t*>(&g_Gh[(size_t)row * DM + col]) =
                (uint32_t)h0 | ((uint32_t)h1 << 16);
            *reinterpret_cast<uint32_t*>(&g_Gl[(size_t)row * DM + col]) =
                (uint32_t)l0 | ((uint32_t)l1 << 16);
            split_bf16(acc[mi][ni][2], h0, l0);
            split_bf16(acc[mi][ni][3], h1, l1);
            *reinterpret_cast<uint32_t*>(&g_Gh[(size_t)(row + 8) * DM + col]) =
                (uint32_t)h0 | ((uint32_t)h1 << 16);
            *reinterpret_cast<uint32_t*>(&g_Gl[(size_t)(row + 8) * DM + col]) =
                (uint32_t)l0 | ((uint32_t)l1 << 16);
        }
    }
}

// ---------------------------------------------------------------- kernel: scores + projV + prefill
// z == 0: aux slab — idx = by*32+bx; idx<512 -> projV; else prefill out = x.
// z in [1,5): scores batch (z-1).
__global__ __launch_bounds__(NTH, 2)
void scores_kernel(float* __restrict__ att, float* __restrict__ out,
                   const float* __restrict__ x) {
    extern __shared__ __align__(128) char smem[];
    const uint32_t sb = smem_u32(smem);
    const int t = threadIdx.x, wid = t >> 5, lane = t & 31;
    const int wr = wid & 3, wc = wid >> 2;

    if (blockIdx.z == 0) {
        const int idx = blockIdx.y * 32 + blockIdx.x;
        if (idx >= 512) {
            // prefill: out = x (residual base), 4096 float4 per CTA
            const int seg = idx - 512;
            #pragma unroll
            for (int r = 0; r < 16; r++) {
                int i = seg * 4096 + r * NTH + t;
                reinterpret_cast<float4*>(out)[i] = reinterpret_cast<const float4*>(x)[i];
            }
            return;
        }
        // projV: V = x * Wv^T, transposed split write
        const int n0 = (idx & 3) * BN;
        const int m0 = (idx >> 2) * BM;

        float acc[2][8][4];
        #pragma unroll
        for (int a = 0; a < 2; a++)
            #pragma unroll
            for (int c = 0; c < 8; c++)
                #pragma unroll
                for (int r = 0; r < 4; r++) acc[a][c][r] = 0.0f;

        run_gemm<true>(sb, t, wr, wc, lane,
                       g_xh + (size_t)m0 * DM, g_xl + (size_t)m0 * DM,
                       g_Wvh + (size_t)n0 * DM, g_Wvl + (size_t)n0 * DM,
                       DM, DM, DM / BK, acc);

        __syncthreads();
        #pragma unroll
        for (int mi = 0; mi < 2; mi++) {
            #pragma unroll
            for (int ni = 0; ni < 8; ni++) {
                #pragma unroll
                for (int r = 0; r < 4; r++) {
                    int srow = wr * 32 + mi * 16 + (lane >> 2) + ((r >> 1) << 3);
                    int dcol = wc * 64 + ni * 8 + ((lane & 3) << 1) + (r & 1);
                    uint16_t h, l;
                    split_bf16(acc[mi][ni][r], h, l);
                    *reinterpret_cast<uint16_t*>(smem + dcol * 256 + srow * 2) = h;
                    *reinterpret_cast<uint16_t*>(smem + 32768 + dcol * 256 + srow * 2) = l;
                }
            }
        }
        __syncthreads();
        const int b = m0 >> 12, s0r = m0 & (SEQ - 1);
        const int d = t >> 1, half = t & 1;
        const uint4* sh = reinterpret_cast<const uint4*>(smem + d * 256 + half * 128);
        const uint4* sl = reinterpret_cast<const uint4*>(smem + 32768 + d * 256 + half * 128);
        size_t o = ((size_t)b * DM + n0 + d) * SEQ + s0r + half * 64;
        uint4* dh = reinterpret_cast<uint4*>(g_Vth + o);
        uint4* dl = reinterpret_cast<uint4*>(g_Vtl + o);
        #pragma unroll
        for (int q = 0; q < 8; q++) { dh[q] = sh[q]; dl[q] = sl[q]; }
        return;
    }

    // scores: S = G x^T
    const int kt = blockIdx.x, qt = blockIdx.y;
    const int b = blockIdx.z - 1;
    float* __restrict__ attb = att + (size_t)b * SEQ * SEQ;

    if (kt > qt) {
        int row = qt * BM + (t >> 1);
        int col = kt * BN + (t & 1) * 64;
        float4 z = make_float4(0.f, 0.f, 0.f, 0.f);
        float4* dst = reinterpret_cast<float4*>(&attb[(size_t)row * SEQ + col]);
        #pragma unroll
        for (int i = 0; i < 16; i++) dst[i] = z;
        return;
    }

    const size_t qr = ((size_t)b * SEQ + qt * BM) * DM;
    const size_t kr = ((size_t)b * SEQ + kt * BN) * DM;

    float acc[2][8][4];
    #pragma unroll
    for (int a = 0; a < 2; a++)
        #pragma unroll
        for (int c = 0; c < 8; c++)
            #pragma unroll
            for (int r = 0; r < 4; r++) acc[a][c][r] = 0.0f;

    // diagonal tile: warps covering cols entirely above the diagonal are masked
    const bool wactive = !(kt == qt && wc == 1 && wr < 2);

    run_gemm<true>(sb, t, wr, wc, lane,
                   g_Gh + qr, g_Gl + qr, g_xh + kr, g_xl + kr,
                   DM, DM, DM / BK, acc, wactive);

    #pragma unroll
    for (int mi = 0; mi < 2; mi++) {
        #pragma unroll
        for (int ni = 0; ni < 8; ni++) {
            int row = qt * BM + wr * 32 + mi * 16 + (lane >> 2);
            int col = kt * BN + wc * 64 + ni * 8 + ((lane & 3) << 1);
            *reinterpret_cast<float2*>(&attb[(size_t)row * SEQ + col]) =
                make_float2(acc[mi][ni][0], acc[mi][ni][1]);
            *reinterpret_cast<float2*>(&attb[(size_t)(row + 8) * SEQ + col]) =
                make_float2(acc[mi][ni][2], acc[mi][ni][3]);
        }
    }
}

// ---------------------------------------------------------------- kernel: softmax (hi-only bf16 emit)
__global__ __launch_bounds__(NTH, 8)
void softmax_kernel(float* __restrict__ att) {
    const int rr = blockIdx.x;
    const int b = rr >> 12;
    const int q = rr & (SEQ - 1);
    float* __restrict__ row = att + (size_t)b * SEQ * SEQ + (size_t)q * SEQ;
    __nv_bfloat16* __restrict__ ph = g_Ph + (size_t)b * SEQ * SEQ + (size_t)q * SEQ;
    const int L = q + 1;
    const int L4 = (L + 3) >> 2;
    const int jmax4 = (((q >> 7) + 1) << 7) >> 2;   // pad to 128-tile, /4

    __shared__ float4 sm4[SEQ / 4];
    __shared__ float red[NTH];
    const int t = threadIdx.x;

    float mx = -INFINITY;
    for (int j4 = t; j4 < L4; j4 += NTH) {
        float4 v = reinterpret_cast<const float4*>(row)[j4];
        int base = j4 << 2;
        float m1 = (base + 1 < L) ? v.y : -INFINITY;
        float m2 = (base + 2 < L) ? v.z : -INFINITY;
        float m3 = (base + 3 < L) ? v.w : -INFINITY;
        mx = fmaxf(mx, fmaxf(fmaxf(v.x, m1), fmaxf(m2, m3)));
        sm4[j4] = v;
    }
    red[t] = mx;
    __syncthreads();
    #pragma unroll
    for (int s = NTH / 2; s > 0; s >>= 1) {
        if (t < s) red[t] = fmaxf(red[t], red[t + s]);
        __syncthreads();
    }
    const float rowmax = red[0];
    __syncthreads();

    float sum = 0.0f;
    for (int j4 = t; j4 < L4; j4 += NTH) {
        float4 v = sm4[j4];
        int base = j4 << 2;
        float e0 = __expf(v.x - rowmax);
        float e1 = (base + 1 < L) ? __expf(v.y - rowmax) : 0.0f;
        float e2 = (base + 2 < L) ? __expf(v.z - rowmax) : 0.0f;
        float e3 = (base + 3 < L) ? __expf(v.w - rowmax) : 0.0f;
        sm4[j4] = make_float4(e0, e1, e2, e3);
        sum += (e0 + e1) + (e2 + e3);
    }
    red[t] = sum;
    __syncthreads();
    #pragma unroll
    for (int s = NTH / 2; s > 0; s >>= 1) {
        if (t < s) red[t] += red[t + s];
        __syncthreads();
    }
    const float inv = 1.0f / red[0];

    for (int j4 = t; j4 < jmax4; j4 += NTH) {
        float4 v = (j4 < L4) ? sm4[j4] : make_float4(0.f, 0.f, 0.f, 0.f);
        float4 o = make_float4(v.x * inv, v.y * inv, v.z * inv, v.w * inv);
        reinterpret_cast<float4*>(row)[j4] = o;
        reinterpret_cast<uint2*>(ph)[j4] =
            make_uint2(pack2_bf16(o.x, o.y), pack2_bf16(o.z, o.w));
    }
}

// ---------------------------------------------------------------- kernel: AV split-K (P hi-only, 2-term; atomic accumulate into out = x)
__global__ __launch_bounds__(NTH, 2)
void av_kernel(float* __restrict__ out) {
    const int b = blockIdx.z;
    const int qt = blockIdx.y >> 2;
    const int seg = blockIdx.y & 3;
    const int n0 = blockIdx.x * BN;
    const int m0 = qt * BM;              // batch-local q row

    const int nch = 4 * (qt + 1);        // total causal chunks for this q tile
    const int c0 = seg * 32;
    if (c0 >= nch) return;               // empty split
    const int nloc = min(32, nch - c0);

    extern __shared__ __align__(128) char smem[];
    const uint32_t sb = smem_u32(smem);
    const int t = threadIdx.x, wid = t >> 5, lane = t & 31;
    const int wr = wid & 3, wc = wid >> 2;

    const size_t pr = ((size_t)b * SEQ + m0) * SEQ + (size_t)c0 * BK;
    const size_t vr = ((size_t)b * DM + n0) * SEQ + (size_t)c0 * BK;

    float acc[2][8][4];
    #pragma unroll
    for (int a = 0; a < 2; a++)
        #pragma unroll
        for (int c = 0; c < 8; c++)
            #pragma unroll
            for (int r = 0; r < 4; r++) acc[a][c][r] = 0.0f;

    run_gemm<false>(sb, t, wr, wc, lane,
                    g_Ph + pr, g_Ph + pr, g_Vth + vr, g_Vtl + vr,
                    SEQ, SEQ, nloc, acc);

    #pragma unroll
    for (int mi = 0; mi < 2; mi++) {
        #pragma unroll
        for (int ni = 0; ni < 8; ni++) {
            int row = m0 + wr * 32 + mi * 16 + (lane >> 2);
            int col = n0 + wc * 64 + ni * 8 + ((lane & 3) << 1);
            size_t base = ((size_t)b * SEQ + row) * DM + col;
            atomicAdd(&out[base],     acc[mi][ni][0]);
            atomicAdd(&out[base + 1], acc[mi][ni][1]);
            size_t base8 = base + (size_t)8 * DM;
            atomicAdd(&out[base8],     acc[mi][ni][2]);
            atomicAdd(&out[base8 + 1], acc[mi][ni][3]);
        }
    }
}

// ---------------------------------------------------------------- launch
extern "C" void kernel_launch(void* const* d_in, const int* in_sizes, int n_in,
                              void* d_out, int out_size) {
    const float* x  = (const float*)d_in[0];
    const float* WQ = (const float*)d_in[1];
    const float* WK = (const float*)d_in[2];
    const float* WV = (const float*)d_in[3];

    float* out = (float*)d_out;                   // [B,S,D]
    float* att = out + (size_t)BSZ * SEQ * DM;    // [B,S,S]

    cudaFuncSetAttribute(projg_kernel,  cudaFuncAttributeMaxDynamicSharedMemorySize, SMEM_TOTAL);
    cudaFuncSetAttribute(scores_kernel, cudaFuncAttributeMaxDynamicSharedMemorySize, SMEM_TOTAL);
    cudaFuncSetAttribute(av_kernel,     cudaFuncAttributeMaxDynamicSharedMemorySize, SMEM_TOTAL);

    // 1) prep: fp32 M gemm FIRST (overlaps), then split Wv, split x
    prep_kernel<<<8512, NTH>>>(x, WQ, WK, WV);

    // 2) G = x M (scale folded)
    projg_kernel<<<dim3(DM / BN, NROWS / BM), NTH, SMEM_TOTAL>>>();

    // 3) aux slab (projV + prefill, z=0) | causal scores S = G x^T (z=1..4)
    scores_kernel<<<dim3(SEQ / BN, SEQ / BM, 5), NTH, SMEM_TOTAL>>>(att, out, x);

    // 4) softmax: fp32 probs to d_out, bf16 hi probs to scratch
    softmax_kernel<<<NROWS, NTH>>>(att);

    // 5) O += P @ V  (split-K, 2-term hi-only P, atomic accumulate)
    av_kernel<<<dim3(DM / BN, (SEQ / BM) * 4, BSZ), NTH, SMEM_TOTAL>>>(out);
}

// round 16
// speedup vs baseline: 1.2993x; 1.1386x over previous
#include <cuda_runtime.h>
#include <cuda_bf16.h>
#include <math.h>
#include <stdint.h>

// ---------------------------------------------------------------- dims
#define BSZ 4
#define SEQ 4096
#define DM  512
#define NROWS (BSZ * SEQ)                 // 16384
#define NTH 256
#define BM 128
#define BN 128
#define BK 32
#define SOFTMAX_SCALE 0.04419417382415922f

// smem stage layout (bf16 tiles, 64-byte rows, SW64 swizzle)
// regions within a stage: AH 0, AL 8192, BH 16384, BL 24576
#define STAGE 32768
#define NSTAGE 3
#define SMEM_TOTAL (NSTAGE * STAGE)       // 98304 bytes -> 2 CTAs/SM

#define SW64(o) ((uint32_t)(o) ^ ((((uint32_t)(o)) >> 3) & 0x30u))

// ---------------------------------------------------------------- scratch
__device__ __nv_bfloat16 g_xh[(size_t)NROWS * DM];
__device__ __nv_bfloat16 g_xl[(size_t)NROWS * DM];
__device__ __nv_bfloat16 g_Wvh[DM * DM];    // Wv    [e][d]
__device__ __nv_bfloat16 g_Wvl[DM * DM];
__device__ __nv_bfloat16 g_MTh[DM * DM];    // (Wq^T Wk)^T * scale  [e][d]
__device__ __nv_bfloat16 g_MTl[DM * DM];
__device__ __nv_bfloat16 g_Gh[(size_t)NROWS * DM];   // G = x*M*scale
__device__ __nv_bfloat16 g_Gl[(size_t)NROWS * DM];
__device__ __nv_bfloat16 g_Vth[(size_t)BSZ * DM * SEQ];  // V^T [b][d][s], hi only
__device__ __nv_bfloat16 g_Ph[(size_t)BSZ * SEQ * SEQ];  // probs hi only

// ---------------------------------------------------------------- helpers
__device__ __forceinline__ uint32_t smem_u32(const void* p) {
    return (uint32_t)__cvta_generic_to_shared(p);
}
__device__ __forceinline__ void ldmx4(uint32_t r[4], uint32_t addr) {
    asm volatile("ldmatrix.sync.aligned.m8n8.x4.shared.b16 {%0,%1,%2,%3}, [%4];"
                 : "=r"(r[0]), "=r"(r[1]), "=r"(r[2]), "=r"(r[3]) : "r"(addr));
}
__device__ __forceinline__ void mma16816(float d[4], const uint32_t a[4],
                                         uint32_t b0, uint32_t b1) {
    asm volatile("mma.sync.aligned.m16n8k16.row.col.f32.bf16.bf16.f32 "
                 "{%0,%1,%2,%3}, {%4,%5,%6,%7}, {%8,%9}, {%0,%1,%2,%3};"
                 : "+f"(d[0]), "+f"(d[1]), "+f"(d[2]), "+f"(d[3])
                 : "r"(a[0]), "r"(a[1]), "r"(a[2]), "r"(a[3]), "r"(b0), "r"(b1));
}
__device__ __forceinline__ void cpasync16(uint32_t dst, const void* src) {
    asm volatile("cp.async.cg.shared.global [%0], [%1], 16;" :: "r"(dst), "l"(src));
}
#define CP_COMMIT() asm volatile("cp.async.commit_group;")
#define CP_WAIT(N)  asm volatile("cp.async.wait_group %0;" :: "n"(N))

__device__ __forceinline__ void split_bf16(float v, uint16_t& h, uint16_t& l) {
    __nv_bfloat16 hb = __float2bfloat16(v);
    float r = v - __bfloat162float(hb);
    h = __bfloat16_as_ushort(hb);
    l = __bfloat16_as_ushort(__float2bfloat16(r));
}

// pack two floats into bf16x2 (lo arg -> low half), round-nearest
__device__ __forceinline__ uint32_t pack2_bf16(float lo, float hi) {
    uint32_t r;
    asm("cvt.rn.bf16x2.f32 %0, %1, %2;" : "=r"(r) : "f"(hi), "f"(lo));
    return r;
}

// ---------------------------------------------------------------- GEMM engine
// Terms: Ah*Bh always; + Ah*Bl if BLON; + Al*Bh if ALON.
// wactive=false: warp skips ldmatrix+mma (loads/syncs unchanged, acc stays 0).
template <bool ALON, bool BLON>
__device__ __forceinline__ void run_gemm(
    uint32_t sb, int t, int wr, int wc, int lane,
    const __nv_bfloat16* Ah, const __nv_bfloat16* Al,
    const __nv_bfloat16* Bh, const __nv_bfloat16* Bl,
    size_t ldA, size_t ldB, int nch, float acc[2][8][4], bool wactive = true)
{
    const int lrow = t >> 2;
    const int lc8 = (t & 3) << 3;
    const uint32_t sdst = SW64((lrow << 6) + (lc8 << 1));
    const __nv_bfloat16* pAh = Ah + (size_t)lrow * ldA + lc8;
    const __nv_bfloat16* pAl = ALON ? (Al + (size_t)lrow * ldA + lc8) : pAh;
    const __nv_bfloat16* pBh = Bh + (size_t)lrow * ldB + lc8;
    const __nv_bfloat16* pBl = BLON ? (Bl + (size_t)lrow * ldB + lc8) : pBh;
    const size_t a64 = (size_t)64 * ldA;
    const size_t b64 = (size_t)64 * ldB;

    const uint32_t aoff = SW64(((wr * 32 + (lane & 15)) << 6) + (((lane >> 4) << 3) << 1));
    const uint32_t boff = SW64(((wc * 64 + ((lane >> 4) << 3) + (lane & 7)) << 6)
                               + ((((lane >> 3) & 1) << 3) << 1));

    uint32_t s0 = sb, s1 = sb + STAGE, s2 = sb + 2 * STAGE;

    auto loadc = [&](uint32_t d) {
        cpasync16(d + sdst,                pAh);
        cpasync16(d + sdst + 4096,         pAh + a64);
        if (ALON) {
            cpasync16(d + 8192 + sdst,        pAl);
            cpasync16(d + 8192 + sdst + 4096, pAl + a64);
        }
        cpasync16(d + 16384 + sdst,        pBh);
        cpasync16(d + 16384 + sdst + 4096, pBh + b64);
        if (BLON) {
            cpasync16(d + 24576 + sdst,        pBl);
            cpasync16(d + 24576 + sdst + 4096, pBl + b64);
        }
        pAh += BK; pBh += BK;
        if (ALON) pAl += BK;
        if (BLON) pBl += BK;
    };

    loadc(s0);
    CP_COMMIT();
    if (nch > 1) loadc(s1);
    CP_COMMIT();

    for (int c = 0; c < nch; c++) {
        CP_WAIT(1);
        __syncthreads();
        if (c + 2 < nch) loadc(s2);
        CP_COMMIT();

        if (wactive) {
            #pragma unroll
            for (int ks = 0; ks < 2; ks++) {
                const uint32_t ab = s0 + (aoff ^ (ks << 5));
                const uint32_t bb = s0 + 16384 + (boff ^ (ks << 5));
                uint32_t ah[2][4], al[2][4];
                ldmx4(ah[0], ab);
                ldmx4(ah[1], ab + 1024);
                if (ALON) {
                    ldmx4(al[0], ab + 8192);
                    ldmx4(al[1], ab + 8192 + 1024);
                }
                #pragma unroll
                for (int p = 0; p < 4; p++) {
                    uint32_t bh[4], bl[4];
                    ldmx4(bh, bb + p * 1024);
                    if (BLON) ldmx4(bl, bb + 8192 + p * 1024);
                    #pragma unroll
                    for (int mi = 0; mi < 2; mi++) {
                        mma16816(acc[mi][2 * p],     ah[mi], bh[0], bh[1]);
                        mma16816(acc[mi][2 * p + 1], ah[mi], bh[2], bh[3]);
                        if (BLON) {
                            mma16816(acc[mi][2 * p],     ah[mi], bl[0], bl[1]);
                            mma16816(acc[mi][2 * p + 1], ah[mi], bl[2], bl[3]);
                        }
                        if (ALON) {
                            mma16816(acc[mi][2 * p],     al[mi], bh[0], bh[1]);
                            mma16816(acc[mi][2 * p + 1], al[mi], bh[2], bh[3]);
                        }
                    }
                }
            }
        }
        uint32_t tmp = s0; s0 = s1; s1 = s2; s2 = tmp;
    }
}

// ---------------------------------------------------------------- kernel: prep
// bid [0,64):      fp32 M gemm: MT[e][d] = scale * sum_f Wk[f][e] Wq[f][d]
// bid [64,320):    split Wv -> g_Wvh/g_Wvl
// bid [320,8512):  split x  -> g_xh/g_xl
__global__ __launch_bounds__(NTH)
void prep_kernel(const float* __restrict__ x, const float* __restrict__ WQ,
                 const float* __restrict__ WK, const float* __restrict__ WV) {
    __shared__ float sa[32][64];   // Wk chunk [f][e]
    __shared__ float sb_[32][64];  // Wq chunk [f][d]
    const int bid = blockIdx.x;
    const int t = threadIdx.x;

    if (bid >= 320) {
        int i = (bid - 320) * NTH + t;     // < 2097152 float4
        float4 v = reinterpret_cast<const float4*>(x)[i];
        uint16_t h0, h1, h2, h3, l0, l1, l2, l3;
        split_bf16(v.x, h0, l0); split_bf16(v.y, h1, l1);
        split_bf16(v.z, h2, l2); split_bf16(v.w, h3, l3);
        reinterpret_cast<uint2*>(g_xh)[i] =
            make_uint2((uint32_t)h0 | ((uint32_t)h1 << 16), (uint32_t)h2 | ((uint32_t)h3 << 16));
        reinterpret_cast<uint2*>(g_xl)[i] =
            make_uint2((uint32_t)l0 | ((uint32_t)l1 << 16), (uint32_t)l2 | ((uint32_t)l3 << 16));
        return;
    }
    if (bid >= 64) {
        int i = (bid - 64) * NTH + t;   // < 65536 float4
        float4 v = reinterpret_cast<const float4*>(WV)[i];
        uint16_t h0, h1, h2, h3, l0, l1, l2, l3;
        split_bf16(v.x, h0, l0); split_bf16(v.y, h1, l1);
        split_bf16(v.z, h2, l2); split_bf16(v.w, h3, l3);
        reinterpret_cast<uint2*>(g_Wvh)[i] =
            make_uint2((uint32_t)h0 | ((uint32_t)h1 << 16), (uint32_t)h2 | ((uint32_t)h3 << 16));
        reinterpret_cast<uint2*>(g_Wvl)[i] =
            make_uint2((uint32_t)l0 | ((uint32_t)l1 << 16), (uint32_t)l2 | ((uint32_t)l3 << 16));
        return;
    }

    // M gemm: 64 CTAs, 64x64 tile each (fp32, CUDA cores)
    const int mb = bid;
    const int e0 = (mb >> 3) * 64;
    const int d0 = (mb & 7) * 64;
    const int tx = t & 15, ty = t >> 4;

    float acc[4][4];
    #pragma unroll
    for (int a = 0; a < 4; a++)
        #pragma unroll
        for (int b = 0; b < 4; b++) acc[a][b] = 0.0f;

    for (int f0 = 0; f0 < DM; f0 += 32) {
        #pragma unroll
        for (int j = 0; j < 2; j++) {
            int idx = t + j * NTH;          // 512 float4 slots
            int row = idx >> 4, c4 = idx & 15;
            *reinterpret_cast<float4*>(&sa[row][c4 * 4]) =
                *reinterpret_cast<const float4*>(&WK[(size_t)(f0 + row) * DM + e0 + c4 * 4]);
            *reinterpret_cast<float4*>(&sb_[row][c4 * 4]) =
                *reinterpret_cast<const float4*>(&WQ[(size_t)(f0 + row) * DM + d0 + c4 * 4]);
        }
        __syncthreads();
        #pragma unroll
        for (int ff = 0; ff < 32; ff++) {
            float ra[4], rb[4];
            #pragma unroll
            for (int a = 0; a < 4; a++) ra[a] = sa[ff][ty * 4 + a];
            #pragma unroll
            for (int b = 0; b < 4; b++) rb[b] = sb_[ff][tx * 4 + b];
            #pragma unroll
            for (int a = 0; a < 4; a++)
                #pragma unroll
                for (int b = 0; b < 4; b++)
                    acc[a][b] += ra[a] * rb[b];
        }
        __syncthreads();
    }

    #pragma unroll
    for (int a = 0; a < 4; a++) {
        #pragma unroll
        for (int b = 0; b < 4; b++) {
            int e = e0 + ty * 4 + a;
            int d = d0 + tx * 4 + b;
            uint16_t h, l;
            split_bf16(acc[a][b] * SOFTMAX_SCALE, h, l);
            g_MTh[(size_t)e * DM + d] = __ushort_as_bfloat16(h);
            g_MTl[(size_t)e * DM + d] = __ushort_as_bfloat16(l);
        }
    }
}

// ---------------------------------------------------------------- kernel: projG (G = x*M)
__global__ __launch_bounds__(NTH, 2)
void projg_kernel() {
    extern __shared__ __align__(128) char smem[];
    const uint32_t sb = smem_u32(smem);
    const int t = threadIdx.x, wid = t >> 5, lane = t & 31;
    const int wr = wid & 3, wc = wid >> 2;
    const int m0 = blockIdx.y * BM;
    const int n0 = blockIdx.x * BN;

    float acc[2][8][4];
    #pragma unroll
    for (int a = 0; a < 2; a++)
        #pragma unroll
        for (int b = 0; b < 8; b++)
            #pragma unroll
            for (int r = 0; r < 4; r++) acc[a][b][r] = 0.0f;

    run_gemm<true, true>(sb, t, wr, wc, lane,
                         g_xh + (size_t)m0 * DM, g_xl + (size_t)m0 * DM,
                         g_MTh + (size_t)n0 * DM, g_MTl + (size_t)n0 * DM,
                         DM, DM, DM / BK, acc);

    #pragma unroll
    for (int mi = 0; mi < 2; mi++) {
        #pragma unroll
        for (int ni = 0; ni < 8; ni++) {
            int row = m0 + wr * 32 + mi * 16 + (lane >> 2);
            int col = n0 + wc * 64 + ni * 8 + ((lane & 3) << 1);
            uint16_t h0, h1, l0, l1;
            split_bf16(acc[mi][ni][0], h0, l0);
            split_bf16(acc[mi][ni][1], h1, l1);
            *reinterpret_cast<uint32_t*>(&g_Gh[(size_t)row * DM + col]) =
                (uint32_t)h0 | ((uint32_t)h1 << 16);
            *reinterpret_cast<uint32_t*>(&g_Gl[(size_t)row * DM + col]) =
                (uint32_t)l0 | ((uint32_t)l1 << 16);
            split_bf16(acc[mi][ni][2], h0, l0);
            split_bf16(acc[mi][ni][3], h1, l1);
            *reinterpret_cast<uint32_t*>(&g_Gh[(size_t)(row + 8) * DM + col]) =
                (uint32_t)h0 | ((uint32_t)h1 << 16);
            *reinterpret_cast<uint32_t*>(&g_Gl[(size_t)(row + 8) * DM + col]) =
                (uint32_t)l0 | ((uint32_t)l1 << 16);
        }
    }
}

// ---------------------------------------------------------------- kernel: scores + projV + prefill
// z == 0: aux slab — idx = by*32+bx; idx<512 -> projV; else prefill out = x.
// z in [1,5): scores batch (z-1).
__global__ __launch_bounds__(NTH, 2)
void scores_kernel(float* __restrict__ att, float* __restrict__ out,
                   const float* __restrict__ x) {
    extern __shared__ __align__(128) char smem[];
    const uint32_t sb = smem_u32(smem);
    const int t = threadIdx.x, wid = t >> 5, lane = t & 31;
    const int wr = wid & 3, wc = wid >> 2;

    if (blockIdx.z == 0) {
        const int idx = blockIdx.y * 32 + blockIdx.x;
        if (idx >= 512) {
            // prefill: out = x (residual base), 4096 float4 per CTA
            const int seg = idx - 512;
            #pragma unroll
            for (int r = 0; r < 16; r++) {
                int i = seg * 4096 + r * NTH + t;
                reinterpret_cast<float4*>(out)[i] = reinterpret_cast<const float4*>(x)[i];
            }
            return;
        }
        // projV: V = x * Wv^T (3-term accurate), transposed hi-only write
        const int n0 = (idx & 3) * BN;
        const int m0 = (idx >> 2) * BM;

        float acc[2][8][4];
        #pragma unroll
        for (int a = 0; a < 2; a++)
            #pragma unroll
            for (int c = 0; c < 8; c++)
                #pragma unroll
                for (int r = 0; r < 4; r++) acc[a][c][r] = 0.0f;

        run_gemm<true, true>(sb, t, wr, wc, lane,
                             g_xh + (size_t)m0 * DM, g_xl + (size_t)m0 * DM,
                             g_Wvh + (size_t)n0 * DM, g_Wvl + (size_t)n0 * DM,
                             DM, DM, DM / BK, acc);

        __syncthreads();
        #pragma unroll
        for (int mi = 0; mi < 2; mi++) {
            #pragma unroll
            for (int ni = 0; ni < 8; ni++) {
                #pragma unroll
                for (int r = 0; r < 4; r++) {
                    int srow = wr * 32 + mi * 16 + (lane >> 2) + ((r >> 1) << 3);
                    int dcol = wc * 64 + ni * 8 + ((lane & 3) << 1) + (r & 1);
                    *reinterpret_cast<uint16_t*>(smem + dcol * 256 + srow * 2) =
                        __bfloat16_as_ushort(__float2bfloat16(acc[mi][ni][r]));
                }
            }
        }
        __syncthreads();
        const int b = m0 >> 12, s0r = m0 & (SEQ - 1);
        const int d = t >> 1, half = t & 1;
        const uint4* sh = reinterpret_cast<const uint4*>(smem + d * 256 + half * 128);
        size_t o = ((size_t)b * DM + n0 + d) * SEQ + s0r + half * 64;
        uint4* dh = reinterpret_cast<uint4*>(g_Vth + o);
        #pragma unroll
        for (int q = 0; q < 8; q++) dh[q] = sh[q];
        return;
    }

    // scores: S = G x^T
    const int kt = blockIdx.x, qt = blockIdx.y;
    const int b = blockIdx.z - 1;
    float* __restrict__ attb = att + (size_t)b * SEQ * SEQ;

    if (kt > qt) {
        int row = qt * BM + (t >> 1);
        int col = kt * BN + (t & 1) * 64;
        float4 z = make_float4(0.f, 0.f, 0.f, 0.f);
        float4* dst = reinterpret_cast<float4*>(&attb[(size_t)row * SEQ + col]);
        #pragma unroll
        for (int i = 0; i < 16; i++) dst[i] = z;
        return;
    }

    const size_t qr = ((size_t)b * SEQ + qt * BM) * DM;
    const size_t kr = ((size_t)b * SEQ + kt * BN) * DM;

    float acc[2][8][4];
    #pragma unroll
    for (int a = 0; a < 2; a++)
        #pragma unroll
        for (int c = 0; c < 8; c++)
            #pragma unroll
            for (int r = 0; r < 4; r++) acc[a][c][r] = 0.0f;

    // diagonal tile: warps covering cols entirely above the diagonal are masked
    const bool wactive = !(kt == qt && wc == 1 && wr < 2);

    run_gemm<true, true>(sb, t, wr, wc, lane,
                         g_Gh + qr, g_Gl + qr, g_xh + kr, g_xl + kr,
                         DM, DM, DM / BK, acc, wactive);

    #pragma unroll
    for (int mi = 0; mi < 2; mi++) {
        #pragma unroll
        for (int ni = 0; ni < 8; ni++) {
            int row = qt * BM + wr * 32 + mi * 16 + (lane >> 2);
            int col = kt * BN + wc * 64 + ni * 8 + ((lane & 3) << 1);
            *reinterpret_cast<float2*>(&attb[(size_t)row * SEQ + col]) =
                make_float2(acc[mi][ni][0], acc[mi][ni][1]);
            *reinterpret_cast<float2*>(&attb[(size_t)(row + 8) * SEQ + col]) =
                make_float2(acc[mi][ni][2], acc[mi][ni][3]);
        }
    }
}

// ---------------------------------------------------------------- kernel: softmax (hi-only bf16 emit)
__global__ __launch_bounds__(NTH, 8)
void softmax_kernel(float* __restrict__ att) {
    const int rr = blockIdx.x;
    const int b = rr >> 12;
    const int q = rr & (SEQ - 1);
    float* __restrict__ row = att + (size_t)b * SEQ * SEQ + (size_t)q * SEQ;
    __nv_bfloat16* __restrict__ ph = g_Ph + (size_t)b * SEQ * SEQ + (size_t)q * SEQ;
    const int L = q + 1;
    const int L4 = (L + 3) >> 2;
    const int jmax4 = (((q >> 7) + 1) << 7) >> 2;   // pad to 128-tile, /4

    __shared__ float4 sm4[SEQ / 4];
    __shared__ float red[NTH];
    const int t = threadIdx.x;

    float mx = -INFINITY;
    for (int j4 = t; j4 < L4; j4 += NTH) {
        float4 v = reinterpret_cast<const float4*>(row)[j4];
        int base = j4 << 2;
        float m1 = (base + 1 < L) ? v.y : -INFINITY;
        float m2 = (base + 2 < L) ? v.z : -INFINITY;
        float m3 = (base + 3 < L) ? v.w : -INFINITY;
        mx = fmaxf(mx, fmaxf(fmaxf(v.x, m1), fmaxf(m2, m3)));
        sm4[j4] = v;
    }
    red[t] = mx;
    __syncthreads();
    #pragma unroll
    for (int s = NTH / 2; s > 0; s >>= 1) {
        if (t < s) red[t] = fmaxf(red[t], red[t + s]);
        __syncthreads();
    }
    const float rowmax = red[0];
    __syncthreads();

    float sum = 0.0f;
    for (int j4 = t; j4 < L4; j4 += NTH) {
        float4 v = sm4[j4];
        int base = j4 << 2;
        float e0 = __expf(v.x - rowmax);
        float e1 = (base + 1 < L) ? __expf(v.y - rowmax) : 0.0f;
        float e2 = (base + 2 < L) ? __expf(v.z - rowmax) : 0.0f;
        float e3 = (base + 3 < L) ? __expf(v.w - rowmax) : 0.0f;
        sm4[j4] = make_float4(e0, e1, e2, e3);
        sum += (e0 + e1) + (e2 + e3);
    }
    red[t] = sum;
    __syncthreads();
    #pragma unroll
    for (int s = NTH / 2; s > 0; s >>= 1) {
        if (t < s) red[t] += red[t + s];
        __syncthreads();
    }
    const float inv = 1.0f / red[0];

    for (int j4 = t; j4 < jmax4; j4 += NTH) {
        float4 v = (j4 < L4) ? sm4[j4] : make_float4(0.f, 0.f, 0.f, 0.f);
        float4 o = make_float4(v.x * inv, v.y * inv, v.z * inv, v.w * inv);
        reinterpret_cast<float4*>(row)[j4] = o;
        reinterpret_cast<uint2*>(ph)[j4] =
            make_uint2(pack2_bf16(o.x, o.y), pack2_bf16(o.z, o.w));
    }
}

// ---------------------------------------------------------------- kernel: AV split-K (P,V hi-only, 1-term; atomic accumulate into out = x)
__global__ __launch_bounds__(NTH, 2)
void av_kernel(float* __restrict__ out) {
    const int b = blockIdx.z;
    const int qt = blockIdx.y >> 2;
    const int seg = blockIdx.y & 3;
    const int n0 = blockIdx.x * BN;
    const int m0 = qt * BM;              // batch-local q row

    const int nch = 4 * (qt + 1);        // total causal chunks for this q tile
    const int c0 = seg * 32;
    if (c0 >= nch) return;               // empty split
    const int nloc = min(32, nch - c0);

    extern __shared__ __align__(128) char smem[];
    const uint32_t sb = smem_u32(smem);
    const int t = threadIdx.x, wid = t >> 5, lane = t & 31;
    const int wr = wid & 3, wc = wid >> 2;

    const size_t pr = ((size_t)b * SEQ + m0) * SEQ + (size_t)c0 * BK;
    const size_t vr = ((size_t)b * DM + n0) * SEQ + (size_t)c0 * BK;

    float acc[2][8][4];
    #pragma unroll
    for (int a = 0; a < 2; a++)
        #pragma unroll
        for (int c = 0; c < 8; c++)
            #pragma unroll
            for (int r = 0; r < 4; r++) acc[a][c][r] = 0.0f;

    run_gemm<false, false>(sb, t, wr, wc, lane,
                           g_Ph + pr, g_Ph + pr, g_Vth + vr, g_Vth + vr,
                           SEQ, SEQ, nloc, acc);

    #pragma unroll
    for (int mi = 0; mi < 2; mi++) {
        #pragma unroll
        for (int ni = 0; ni < 8; ni++) {
            int row = m0 + wr * 32 + mi * 16 + (lane >> 2);
            int col = n0 + wc * 64 + ni * 8 + ((lane & 3) << 1);
            size_t base = ((size_t)b * SEQ + row) * DM + col;
            atomicAdd(&out[base],     acc[mi][ni][0]);
            atomicAdd(&out[base + 1], acc[mi][ni][1]);
            size_t base8 = base + (size_t)8 * DM;
            atomicAdd(&out[base8],     acc[mi][ni][2]);
            atomicAdd(&out[base8 + 1], acc[mi][ni][3]);
        }
    }
}

// ---------------------------------------------------------------- launch
extern "C" void kernel_launch(void* const* d_in, const int* in_sizes, int n_in,
                              void* d_out, int out_size) {
    const float* x  = (const float*)d_in[0];
    const float* WQ = (const float*)d_in[1];
    const float* WK = (const float*)d_in[2];
    const float* WV = (const float*)d_in[3];

    float* out = (float*)d_out;                   // [B,S,D]
    float* att = out + (size_t)BSZ * SEQ * DM;    // [B,S,S]

    cudaFuncSetAttribute(projg_kernel,  cudaFuncAttributeMaxDynamicSharedMemorySize, SMEM_TOTAL);
    cudaFuncSetAttribute(scores_kernel, cudaFuncAttributeMaxDynamicSharedMemorySize, SMEM_TOTAL);
    cudaFuncSetAttribute(av_kernel,     cudaFuncAttributeMaxDynamicSharedMemorySize, SMEM_TOTAL);

    // 1) prep: fp32 M gemm FIRST (overlaps), then split Wv, split x
    prep_kernel<<<8512, NTH>>>(x, WQ, WK, WV);

    // 2) G = x M (scale folded)
    projg_kernel<<<dim3(DM / BN, NROWS / BM), NTH, SMEM_TOTAL>>>();

    // 3) aux slab (projV + prefill, z=0) | causal scores S = G x^T (z=1..4)
    scores_kernel<<<dim3(SEQ / BN, SEQ / BM, 5), NTH, SMEM_TOTAL>>>(att, out, x);

    // 4) softmax: fp32 probs to d_out, bf16 hi probs to scratch
    softmax_kernel<<<NROWS, NTH>>>(att);

    // 5) O += P @ V  (split-K, 1-term hi-only, atomic accumulate)
    av_kernel<<<dim3(DM / BN, (SEQ / BM) * 4, BSZ), NTH, SMEM_TOTAL>>>(out);
}

// round 17
// speedup vs baseline: 1.3023x; 1.0023x over previous
#include <cuda_runtime.h>
#include <cuda_bf16.h>
#include <math.h>
#include <stdint.h>

// ---------------------------------------------------------------- dims
#define BSZ 4
#define SEQ 4096
#define DM  512
#define NROWS (BSZ * SEQ)                 // 16384
#define NTH 256
#define BM 128
#define BN 128
#define BK 32
#define SOFTMAX_SCALE 0.04419417382415922f

// smem stage layout (bf16 tiles, 64-byte rows, SW64 swizzle)
// regions within a stage: AH 0, AL 8192, BH 16384, BL 24576
#define STAGE 32768
#define NSTAGE 3
#define SMEM_TOTAL (NSTAGE * STAGE)       // 98304 bytes -> 2 CTAs/SM

#define SW64(o) ((uint32_t)(o) ^ ((((uint32_t)(o)) >> 3) & 0x30u))

// ---------------------------------------------------------------- scratch
__device__ __nv_bfloat16 g_xh[(size_t)NROWS * DM];
__device__ __nv_bfloat16 g_xl[(size_t)NROWS * DM];
__device__ __nv_bfloat16 g_Wvh[DM * DM];    // Wv    [e][d]
__device__ __nv_bfloat16 g_Wvl[DM * DM];
__device__ __nv_bfloat16 g_MTh[DM * DM];    // (Wq^T Wk)^T * scale  [e][d]
__device__ __nv_bfloat16 g_MTl[DM * DM];
__device__ __nv_bfloat16 g_Gh[(size_t)NROWS * DM];   // G = x*M*scale
__device__ __nv_bfloat16 g_Gl[(size_t)NROWS * DM];
__device__ __nv_bfloat16 g_Vth[(size_t)BSZ * DM * SEQ];  // V^T [b][d][s], hi only
__device__ __nv_bfloat16 g_Ph[(size_t)BSZ * SEQ * SEQ];  // probs hi only

// ---------------------------------------------------------------- helpers
__device__ __forceinline__ uint32_t smem_u32(const void* p) {
    return (uint32_t)__cvta_generic_to_shared(p);
}
__device__ __forceinline__ void ldmx4(uint32_t r[4], uint32_t addr) {
    asm volatile("ldmatrix.sync.aligned.m8n8.x4.shared.b16 {%0,%1,%2,%3}, [%4];"
                 : "=r"(r[0]), "=r"(r[1]), "=r"(r[2]), "=r"(r[3]) : "r"(addr));
}
__device__ __forceinline__ void mma16816(float d[4], const uint32_t a[4],
                                         uint32_t b0, uint32_t b1) {
    asm volatile("mma.sync.aligned.m16n8k16.row.col.f32.bf16.bf16.f32 "
                 "{%0,%1,%2,%3}, {%4,%5,%6,%7}, {%8,%9}, {%0,%1,%2,%3};"
                 : "+f"(d[0]), "+f"(d[1]), "+f"(d[2]), "+f"(d[3])
                 : "r"(a[0]), "r"(a[1]), "r"(a[2]), "r"(a[3]), "r"(b0), "r"(b1));
}
__device__ __forceinline__ void cpasync16(uint32_t dst, const void* src) {
    asm volatile("cp.async.cg.shared.global [%0], [%1], 16;" :: "r"(dst), "l"(src));
}
#define CP_COMMIT() asm volatile("cp.async.commit_group;")
#define CP_WAIT(N)  asm volatile("cp.async.wait_group %0;" :: "n"(N))

__device__ __forceinline__ void split_bf16(float v, uint16_t& h, uint16_t& l) {
    __nv_bfloat16 hb = __float2bfloat16(v);
    float r = v - __bfloat162float(hb);
    h = __bfloat16_as_ushort(hb);
    l = __bfloat16_as_ushort(__float2bfloat16(r));
}

// pack two floats into bf16x2 (lo arg -> low half), round-nearest
__device__ __forceinline__ uint32_t pack2_bf16(float lo, float hi) {
    uint32_t r;
    asm("cvt.rn.bf16x2.f32 %0, %1, %2;" : "=r"(r) : "f"(hi), "f"(lo));
    return r;
}

// ---------------------------------------------------------------- GEMM engine
// Terms: Ah*Bh always; + Ah*Bl if BLON; + Al*Bh if ALON.
// wactive=false: warp skips ldmatrix+mma (loads/syncs unchanged, acc stays 0).
template <bool ALON, bool BLON>
__device__ __forceinline__ void run_gemm(
    uint32_t sb, int t, int wr, int wc, int lane,
    const __nv_bfloat16* Ah, const __nv_bfloat16* Al,
    const __nv_bfloat16* Bh, const __nv_bfloat16* Bl,
    size_t ldA, size_t ldB, int nch, float acc[2][8][4], bool wactive = true)
{
    const int lrow = t >> 2;
    const int lc8 = (t & 3) << 3;
    const uint32_t sdst = SW64((lrow << 6) + (lc8 << 1));
    const __nv_bfloat16* pAh = Ah + (size_t)lrow * ldA + lc8;
    const __nv_bfloat16* pAl = ALON ? (Al + (size_t)lrow * ldA + lc8) : pAh;
    const __nv_bfloat16* pBh = Bh + (size_t)lrow * ldB + lc8;
    const __nv_bfloat16* pBl = BLON ? (Bl + (size_t)lrow * ldB + lc8) : pBh;
    const size_t a64 = (size_t)64 * ldA;
    const size_t b64 = (size_t)64 * ldB;

    const uint32_t aoff = SW64(((wr * 32 + (lane & 15)) << 6) + (((lane >> 4) << 3) << 1));
    const uint32_t boff = SW64(((wc * 64 + ((lane >> 4) << 3) + (lane & 7)) << 6)
                               + ((((lane >> 3) & 1) << 3) << 1));

    uint32_t s0 = sb, s1 = sb + STAGE, s2 = sb + 2 * STAGE;

    auto loadc = [&](uint32_t d) {
        cpasync16(d + sdst,                pAh);
        cpasync16(d + sdst + 4096,         pAh + a64);
        if (ALON) {
            cpasync16(d + 8192 + sdst,        pAl);
            cpasync16(d + 8192 + sdst + 4096, pAl + a64);
        }
        cpasync16(d + 16384 + sdst,        pBh);
        cpasync16(d + 16384 + sdst + 4096, pBh + b64);
        if (BLON) {
            cpasync16(d + 24576 + sdst,        pBl);
            cpasync16(d + 24576 + sdst + 4096, pBl + b64);
        }
        pAh += BK; pBh += BK;
        if (ALON) pAl += BK;
        if (BLON) pBl += BK;
    };

    loadc(s0);
    CP_COMMIT();
    if (nch > 1) loadc(s1);
    CP_COMMIT();

    for (int c = 0; c < nch; c++) {
        CP_WAIT(1);
        __syncthreads();
        if (c + 2 < nch) loadc(s2);
        CP_COMMIT();

        if (wactive) {
            #pragma unroll
            for (int ks = 0; ks < 2; ks++) {
                const uint32_t ab = s0 + (aoff ^ (ks << 5));
                const uint32_t bb = s0 + 16384 + (boff ^ (ks << 5));
                uint32_t ah[2][4], al[2][4];
                ldmx4(ah[0], ab);
                ldmx4(ah[1], ab + 1024);
                if (ALON) {
                    ldmx4(al[0], ab + 8192);
                    ldmx4(al[1], ab + 8192 + 1024);
                }
                #pragma unroll
                for (int p = 0; p < 4; p++) {
                    uint32_t bh[4], bl[4];
                    ldmx4(bh, bb + p * 1024);
                    if (BLON) ldmx4(bl, bb + 8192 + p * 1024);
                    #pragma unroll
                    for (int mi = 0; mi < 2; mi++) {
                        mma16816(acc[mi][2 * p],     ah[mi], bh[0], bh[1]);
                        mma16816(acc[mi][2 * p + 1], ah[mi], bh[2], bh[3]);
                        if (BLON) {
                            mma16816(acc[mi][2 * p],     ah[mi], bl[0], bl[1]);
                            mma16816(acc[mi][2 * p + 1], ah[mi], bl[2], bl[3]);
                        }
                        if (ALON) {
                            mma16816(acc[mi][2 * p],     al[mi], bh[0], bh[1]);
                            mma16816(acc[mi][2 * p + 1], al[mi], bh[2], bh[3]);
                        }
                    }
                }
            }
        }
        uint32_t tmp = s0; s0 = s1; s1 = s2; s2 = tmp;
    }
}

// ---------------------------------------------------------------- kernel: prep
// bid [0,64):      fp32 M gemm: MT[e][d] = scale * sum_f Wk[f][e] Wq[f][d]
// bid [64,320):    split Wv -> g_Wvh/g_Wvl
// bid [320,8512):  split x  -> g_xh/g_xl
__global__ __launch_bounds__(NTH)
void prep_kernel(const float* __restrict__ x, const float* __restrict__ WQ,
                 const float* __restrict__ WK, const float* __restrict__ WV) {
    __shared__ float sa[32][64];   // Wk chunk [f][e]
    __shared__ float sb_[32][64];  // Wq chunk [f][d]
    const int bid = blockIdx.x;
    const int t = threadIdx.x;

    if (bid >= 320) {
        int i = (bid - 320) * NTH + t;     // < 2097152 float4
        float4 v = reinterpret_cast<const float4*>(x)[i];
        uint16_t h0, h1, h2, h3, l0, l1, l2, l3;
        split_bf16(v.x, h0, l0); split_bf16(v.y, h1, l1);
        split_bf16(v.z, h2, l2); split_bf16(v.w, h3, l3);
        reinterpret_cast<uint2*>(g_xh)[i] =
            make_uint2((uint32_t)h0 | ((uint32_t)h1 << 16), (uint32_t)h2 | ((uint32_t)h3 << 16));
        reinterpret_cast<uint2*>(g_xl)[i] =
            make_uint2((uint32_t)l0 | ((uint32_t)l1 << 16), (uint32_t)l2 | ((uint32_t)l3 << 16));
        return;
    }
    if (bid >= 64) {
        int i = (bid - 64) * NTH + t;   // < 65536 float4
        float4 v = reinterpret_cast<const float4*>(WV)[i];
        uint16_t h0, h1, h2, h3, l0, l1, l2, l3;
        split_bf16(v.x, h0, l0); split_bf16(v.y, h1, l1);
        split_bf16(v.z, h2, l2); split_bf16(v.w, h3, l3);
        reinterpret_cast<uint2*>(g_Wvh)[i] =
            make_uint2((uint32_t)h0 | ((uint32_t)h1 << 16), (uint32_t)h2 | ((uint32_t)h3 << 16));
        reinterpret_cast<uint2*>(g_Wvl)[i] =
            make_uint2((uint32_t)l0 | ((uint32_t)l1 << 16), (uint32_t)l2 | ((uint32_t)l3 << 16));
        return;
    }

    // M gemm: 64 CTAs, 64x64 tile each (fp32, CUDA cores)
    const int mb = bid;
    const int e0 = (mb >> 3) * 64;
    const int d0 = (mb & 7) * 64;
    const int tx = t & 15, ty = t >> 4;

    float acc[4][4];
    #pragma unroll
    for (int a = 0; a < 4; a++)
        #pragma unroll
        for (int b = 0; b < 4; b++) acc[a][b] = 0.0f;

    for (int f0 = 0; f0 < DM; f0 += 32) {
        #pragma unroll
        for (int j = 0; j < 2; j++) {
            int idx = t + j * NTH;          // 512 float4 slots
            int row = idx >> 4, c4 = idx & 15;
            *reinterpret_cast<float4*>(&sa[row][c4 * 4]) =
                *reinterpret_cast<const float4*>(&WK[(size_t)(f0 + row) * DM + e0 + c4 * 4]);
            *reinterpret_cast<float4*>(&sb_[row][c4 * 4]) =
                *reinterpret_cast<const float4*>(&WQ[(size_t)(f0 + row) * DM + d0 + c4 * 4]);
        }
        __syncthreads();
        #pragma unroll
        for (int ff = 0; ff < 32; ff++) {
            float ra[4], rb[4];
            #pragma unroll
            for (int a = 0; a < 4; a++) ra[a] = sa[ff][ty * 4 + a];
            #pragma unroll
            for (int b = 0; b < 4; b++) rb[b] = sb_[ff][tx * 4 + b];
            #pragma unroll
            for (int a = 0; a < 4; a++)
                #pragma unroll
                for (int b = 0; b < 4; b++)
                    acc[a][b] += ra[a] * rb[b];
        }
        __syncthreads();
    }

    #pragma unroll
    for (int a = 0; a < 4; a++) {
        #pragma unroll
        for (int b = 0; b < 4; b++) {
            int e = e0 + ty * 4 + a;
            int d = d0 + tx * 4 + b;
            uint16_t h, l;
            split_bf16(acc[a][b] * SOFTMAX_SCALE, h, l);
            g_MTh[(size_t)e * DM + d] = __ushort_as_bfloat16(h);
            g_MTl[(size_t)e * DM + d] = __ushort_as_bfloat16(l);
        }
    }
}

// ---------------------------------------------------------------- kernel: projG (G = x*M)
__global__ __launch_bounds__(NTH, 2)
void projg_kernel() {
    extern __shared__ __align__(128) char smem[];
    const uint32_t sb = smem_u32(smem);
    const int t = threadIdx.x, wid = t >> 5, lane = t & 31;
    const int wr = wid & 3, wc = wid >> 2;
    const int m0 = blockIdx.y * BM;
    const int n0 = blockIdx.x * BN;

    float acc[2][8][4];
    #pragma unroll
    for (int a = 0; a < 2; a++)
        #pragma unroll
        for (int b = 0; b < 8; b++)
            #pragma unroll
            for (int r = 0; r < 4; r++) acc[a][b][r] = 0.0f;

    run_gemm<true, true>(sb, t, wr, wc, lane,
                         g_xh + (size_t)m0 * DM, g_xl + (size_t)m0 * DM,
                         g_MTh + (size_t)n0 * DM, g_MTl + (size_t)n0 * DM,
                         DM, DM, DM / BK, acc);

    #pragma unroll
    for (int mi = 0; mi < 2; mi++) {
        #pragma unroll
        for (int ni = 0; ni < 8; ni++) {
            int row = m0 + wr * 32 + mi * 16 + (lane >> 2);
            int col = n0 + wc * 64 + ni * 8 + ((lane & 3) << 1);
            uint16_t h0, h1, l0, l1;
            split_bf16(acc[mi][ni][0], h0, l0);
            split_bf16(acc[mi][ni][1], h1, l1);
            *reinterpret_cast<uint32_t*>(&g_Gh[(size_t)row * DM + col]) =
                (uint32_t)h0 | ((uint32_t)h1 << 16);
            *reinterpret_cast<uint32_t*>(&g_Gl[(size_t)row * DM + col]) =
                (uint32_t)l0 | ((uint32_t)l1 << 16);
            split_bf16(acc[mi][ni][2], h0, l0);
            split_bf16(acc[mi][ni][3], h1, l1);
            *reinterpret_cast<uint32_t*>(&g_Gh[(size_t)(row + 8) * DM + col]) =
                (uint32_t)h0 | ((uint32_t)h1 << 16);
            *reinterpret_cast<uint32_t*>(&g_Gl[(size_t)(row + 8) * DM + col]) =
                (uint32_t)l0 | ((uint32_t)l1 << 16);
        }
    }
}

// ---------------------------------------------------------------- kernel: scores + projV + prefill
// z == 0: aux slab — idx = by*32+bx; idx<512 -> projV; else prefill out = x.
// z in [1,5): scores batch (z-1).
__global__ __launch_bounds__(NTH, 2)
void scores_kernel(float* __restrict__ att, float* __restrict__ out,
                   const float* __restrict__ x) {
    extern __shared__ __align__(128) char smem[];
    const uint32_t sb = smem_u32(smem);
    const int t = threadIdx.x, wid = t >> 5, lane = t & 31;
    const int wr = wid & 3, wc = wid >> 2;

    if (blockIdx.z == 0) {
        const int idx = blockIdx.y * 32 + blockIdx.x;
        if (idx >= 512) {
            // prefill: out = x (residual base), 4096 float4 per CTA
            const int seg = idx - 512;
            #pragma unroll
            for (int r = 0; r < 16; r++) {
                int i = seg * 4096 + r * NTH + t;
                reinterpret_cast<float4*>(out)[i] = reinterpret_cast<const float4*>(x)[i];
            }
            return;
        }
        // projV: V = x * Wv^T (3-term accurate), transposed hi-only write
        const int n0 = (idx & 3) * BN;
        const int m0 = (idx >> 2) * BM;

        float acc[2][8][4];
        #pragma unroll
        for (int a = 0; a < 2; a++)
            #pragma unroll
            for (int c = 0; c < 8; c++)
                #pragma unroll
                for (int r = 0; r < 4; r++) acc[a][c][r] = 0.0f;

        run_gemm<true, true>(sb, t, wr, wc, lane,
                             g_xh + (size_t)m0 * DM, g_xl + (size_t)m0 * DM,
                             g_Wvh + (size_t)n0 * DM, g_Wvl + (size_t)n0 * DM,
                             DM, DM, DM / BK, acc);

        __syncthreads();
        #pragma unroll
        for (int mi = 0; mi < 2; mi++) {
            #pragma unroll
            for (int ni = 0; ni < 8; ni++) {
                #pragma unroll
                for (int r = 0; r < 4; r++) {
                    int srow = wr * 32 + mi * 16 + (lane >> 2) + ((r >> 1) << 3);
                    int dcol = wc * 64 + ni * 8 + ((lane & 3) << 1) + (r & 1);
                    *reinterpret_cast<uint16_t*>(smem + dcol * 256 + srow * 2) =
                        __bfloat16_as_ushort(__float2bfloat16(acc[mi][ni][r]));
                }
            }
        }
        __syncthreads();
        const int b = m0 >> 12, s0r = m0 & (SEQ - 1);
        const int d = t >> 1, half = t & 1;
        const uint4* sh = reinterpret_cast<const uint4*>(smem + d * 256 + half * 128);
        size_t o = ((size_t)b * DM + n0 + d) * SEQ + s0r + half * 64;
        uint4* dh = reinterpret_cast<uint4*>(g_Vth + o);
        #pragma unroll
        for (int q = 0; q < 8; q++) dh[q] = sh[q];
        return;
    }

    // scores: S = G x^T
    const int kt = blockIdx.x, qt = blockIdx.y;
    const int b = blockIdx.z - 1;
    float* __restrict__ attb = att + (size_t)b * SEQ * SEQ;

    if (kt > qt) {
        int row = qt * BM + (t >> 1);
        int col = kt * BN + (t & 1) * 64;
        float4 z = make_float4(0.f, 0.f, 0.f, 0.f);
        float4* dst = reinterpret_cast<float4*>(&attb[(size_t)row * SEQ + col]);
        #pragma unroll
        for (int i = 0; i < 16; i++) dst[i] = z;
        return;
    }

    const size_t qr = ((size_t)b * SEQ + qt * BM) * DM;
    const size_t kr = ((size_t)b * SEQ + kt * BN) * DM;

    float acc[2][8][4];
    #pragma unroll
    for (int a = 0; a < 2; a++)
        #pragma unroll
        for (int c = 0; c < 8; c++)
            #pragma unroll
            for (int r = 0; r < 4; r++) acc[a][c][r] = 0.0f;

    // diagonal tile: warps covering cols entirely above the diagonal are masked
    const bool wactive = !(kt == qt && wc == 1 && wr < 2);

    run_gemm<true, true>(sb, t, wr, wc, lane,
                         g_Gh + qr, g_Gl + qr, g_xh + kr, g_xl + kr,
                         DM, DM, DM / BK, acc, wactive);

    #pragma unroll
    for (int mi = 0; mi < 2; mi++) {
        #pragma unroll
        for (int ni = 0; ni < 8; ni++) {
            int row = qt * BM + wr * 32 + mi * 16 + (lane >> 2);
            int col = kt * BN + wc * 64 + ni * 8 + ((lane & 3) << 1);
            *reinterpret_cast<float2*>(&attb[(size_t)row * SEQ + col]) =
                make_float2(acc[mi][ni][0], acc[mi][ni][1]);
            *reinterpret_cast<float2*>(&attb[(size_t)(row + 8) * SEQ + col]) =
                make_float2(acc[mi][ni][2], acc[mi][ni][3]);
        }
    }
}

// ---------------------------------------------------------------- kernel: softmax (hi-only bf16 emit)
__global__ __launch_bounds__(NTH, 8)
void softmax_kernel(float* __restrict__ att) {
    const int rr = blockIdx.x;
    const int b = rr >> 12;
    const int q = rr & (SEQ - 1);
    float* __restrict__ row = att + (size_t)b * SEQ * SEQ + (size_t)q * SEQ;
    __nv_bfloat16* __restrict__ ph = g_Ph + (size_t)b * SEQ * SEQ + (size_t)q * SEQ;
    const int L = q + 1;
    const int L4 = (L + 3) >> 2;
    const int jmax4 = (((q >> 7) + 1) << 7) >> 2;   // pad to 128-tile, /4

    __shared__ float4 sm4[SEQ / 4];
    __shared__ float red[NTH];
    const int t = threadIdx.x;

    float mx = -INFINITY;
    for (int j4 = t; j4 < L4; j4 += NTH) {
        float4 v = reinterpret_cast<const float4*>(row)[j4];
        int base = j4 << 2;
        float m1 = (base + 1 < L) ? v.y : -INFINITY;
        float m2 = (base + 2 < L) ? v.z : -INFINITY;
        float m3 = (base + 3 < L) ? v.w : -INFINITY;
        mx = fmaxf(mx, fmaxf(fmaxf(v.x, m1), fmaxf(m2, m3)));
        sm4[j4] = v;
    }
    red[t] = mx;
    __syncthreads();
    #pragma unroll
    for (int s = NTH / 2; s > 0; s >>= 1) {
        if (t < s) red[t] = fmaxf(red[t], red[t + s]);
        __syncthreads();
    }
    const float rowmax = red[0];
    __syncthreads();

    float sum = 0.0f;
    for (int j4 = t; j4 < L4; j4 += NTH) {
        float4 v = sm4[j4];
        int base = j4 << 2;
        float e0 = __expf(v.x - rowmax);
        float e1 = (base + 1 < L) ? __expf(v.y - rowmax) : 0.0f;
        float e2 = (base + 2 < L) ? __expf(v.z - rowmax) : 0.0f;
        float e3 = (base + 3 < L) ? __expf(v.w - rowmax) : 0.0f;
        sm4[j4] = make_float4(e0, e1, e2, e3);
        sum += (e0 + e1) + (e2 + e3);
    }
    red[t] = sum;
    __syncthreads();
    #pragma unroll
    for (int s = NTH / 2; s > 0; s >>= 1) {
        if (t < s) red[t] += red[t + s];
        __syncthreads();
    }
    const float inv = 1.0f / red[0];

    for (int j4 = t; j4 < jmax4; j4 += NTH) {
        float4 v = (j4 < L4) ? sm4[j4] : make_float4(0.f, 0.f, 0.f, 0.f);
        float4 o = make_float4(v.x * inv, v.y * inv, v.z * inv, v.w * inv);
        reinterpret_cast<float4*>(row)[j4] = o;
        reinterpret_cast<uint2*>(ph)[j4] =
            make_uint2(pack2_bf16(o.x, o.y), pack2_bf16(o.z, o.w));
    }
}

// ---------------------------------------------------------------- kernel: AV split-K (P,V hi-only, 1-term; atomic accumulate into out = x)
__global__ __launch_bounds__(NTH, 2)
void av_kernel(float* __restrict__ out) {
    const int b = blockIdx.z;
    const int qt = blockIdx.y >> 2;
    const int seg = blockIdx.y & 3;
    const int n0 = blockIdx.x * BN;
    const int m0 = qt * BM;              // batch-local q row

    const int nch = 4 * (qt + 1);        // total causal chunks for this q tile
    const int c0 = seg * 32;
    if (c0 >= nch) return;               // empty split
    const int nloc = min(32, nch - c0);

    extern __shared__ __align__(128) char smem[];
    const uint32_t sb = smem_u32(smem);
    const int t = threadIdx.x, wid = t >> 5, lane = t & 31;
    const int wr = wid & 3, wc = wid >> 2;

    const size_t pr = ((size_t)b * SEQ + m0) * SEQ + (size_t)c0 * BK;
    const size_t vr = ((size_t)b * DM + n0) * SEQ + (size_t)c0 * BK;

    float acc[2][8][4];
    #pragma unroll
    for (int a = 0; a < 2; a++)
        #pragma unroll
        for (int c = 0; c < 8; c++)
            #pragma unroll
            for (int r = 0; r < 4; r++) acc[a][c][r] = 0.0f;

    run_gemm<false, false>(sb, t, wr, wc, lane,
                           g_Ph + pr, g_Ph + pr, g_Vth + vr, g_Vth + vr,
                           SEQ, SEQ, nloc, acc);

    #pragma unroll
    for (int mi = 0; mi < 2; mi++) {
        #pragma unroll
        for (int ni = 0; ni < 8; ni++) {
            int row = m0 + wr * 32 + mi * 16 + (lane >> 2);
            int col = n0 + wc * 64 + ni * 8 + ((lane & 3) << 1);
            size_t base = ((size_t)b * SEQ + row) * DM + col;
            atomicAdd(&out[base],     acc[mi][ni][0]);
            atomicAdd(&out[base + 1], acc[mi][ni][1]);
            size_t base8 = base + (size_t)8 * DM;
            atomicAdd(&out[base8],     acc[mi][ni][2]);
            atomicAdd(&out[base8 + 1], acc[mi][ni][3]);
        }
    }
}

// ---------------------------------------------------------------- launch
extern "C" void kernel_launch(void* const* d_in, const int* in_sizes, int n_in,
                              void* d_out, int out_size) {
    const float* x  = (const float*)d_in[0];
    const float* WQ = (const float*)d_in[1];
    const float* WK = (const float*)d_in[2];
    const float* WV = (const float*)d_in[3];

    float* out = (float*)d_out;                   // [B,S,D]
    float* att = out + (size_t)BSZ * SEQ * DM;    // [B,S,S]

    cudaFuncSetAttribute(projg_kernel,  cudaFuncAttributeMaxDynamicSharedMemorySize, SMEM_TOTAL);
    cudaFuncSetAttribute(scores_kernel, cudaFuncAttributeMaxDynamicSharedMemorySize, SMEM_TOTAL);
    cudaFuncSetAttribute(av_kernel,     cudaFuncAttributeMaxDynamicSharedMemorySize, SMEM_TOTAL);

    // 1) prep: fp32 M gemm FIRST (overlaps), then split Wv, split x
    prep_kernel<<<8512, NTH>>>(x, WQ, WK, WV);

    // 2) G = x M (scale folded)
    projg_kernel<<<dim3(DM / BN, NROWS / BM), NTH, SMEM_TOTAL>>>();

    // 3) aux slab (projV + prefill, z=0) | causal scores S = G x^T (z=1..4)
    scores_kernel<<<dim3(SEQ / BN, SEQ / BM, 5), NTH, SMEM_TOTAL>>>(att, out, x);

    // 4) softmax: fp32 probs to d_out, bf16 hi probs to scratch
    softmax_kernel<<<NROWS, NTH>>>(att);

    // 5) O += P @ V  (split-K, 1-term hi-only, atomic accumulate)
    av_kernel<<<dim3(DM / BN, (SEQ / BM) * 4, BSZ), NTH, SMEM_TOTAL>>>(out);
}